// round 10
// baseline (speedup 1.0000x reference)
#include <cuda_runtime.h>
#include <cstdint>

// SLAYER constants
#define ALPHA_F 0.90483741803595952f
#define THETA_F 10.0f

// Problem dims
#define BB   32
#define CIN  156
#define TT   2048
#define HID  512
#define NOUT 20
#define OUTT (TT + CIN)   // 2204

typedef unsigned long long ull;

// ---------------------------------------------------------------------------
// Scratch
// ---------------------------------------------------------------------------
__device__ unsigned char g_s1u8[(size_t)BB * HID * TT];  // branch1 layer1 spikes (u8)
__device__ float         g_a2[(size_t)BB * NOUT * TT];   // branch1 layer2 pre-acts
__device__ float         g_l1[(size_t)BB * CIN * HID];   // branch2 spikes, [b][c][h]
__device__ float         g_l2[(size_t)BB * NOUT * CIN];  // branch2 layer2 pre-acts

// packed fp32x2 FMA: two independent rn-rounded fp32 FMAs (bitwise == scalar fmaf)
__device__ __forceinline__ void ffma2(ull& d, ull a, ull b) {
    asm("fma.rn.f32x2 %0, %1, %2, %0;" : "+l"(d) : "l"(a), "l"(b));
}
__device__ __forceinline__ ull dup2(float v) {
    float2 f = make_float2(v, v);
    return *(ull*)&f;
}

// ===========================================================================
// FUSED branch1 layer1 + psp + spike.  (unchanged — FMA-bound)
// ===========================================================================
#define B1_SMEM 135424

__global__ __launch_bounds__(512) void k_b1l1_psp(const float* __restrict__ X,
                                                  const float* __restrict__ W1) {
    extern __shared__ char sm[];
    ull*   Asd = (ull*)sm;                         // [2][16*133]
    float* Bsf = (float*)(sm + 34048);             // [2][16*132]
    float* Ct  = (float*)(sm + 50944);             // [128][132]
    unsigned char* Cu8 = (unsigned char*)(sm + 118528);

    const int b  = blockIdx.y;
    const int h0 = blockIdx.x * 128;
    const int tid = threadIdx.x;
    const int tx = tid & 31, ty = tid >> 5;
    const int ha = tid >> 2, cq = tid & 3;         // A-fill map
    const int kb = tid >> 5, t4 = tid & 31;        // B-fill map
    const float* Xb = X + (size_t)b * CIN * TT;
    const float* Wr = W1 + (size_t)(h0 + ha) * CIN;

    float ycar = 0.0f;                             // psp carry (threads 0..127)

    for (int t0 = 0; t0 < TT; t0 += 128) {
        ull acc[8][2];
#pragma unroll
        for (int i = 0; i < 8; i++) { acc[i][0] = 0ULL; acc[i][1] = 0ULL; }

        float4 va, vb;
        {
            int c = cq * 4;
            va = (c < CIN) ? *(const float4*)(Wr + c) : make_float4(0.f,0.f,0.f,0.f);
            vb = (kb < CIN) ? *(const float4*)(Xb + (size_t)kb * TT + t0 + t4 * 4)
                            : make_float4(0.f,0.f,0.f,0.f);
        }
        {
            ull* Ad = Asd;  float* Bd = Bsf;
            Ad[(cq*4+0)*133 + ha] = dup2(va.x);
            Ad[(cq*4+1)*133 + ha] = dup2(va.y);
            Ad[(cq*4+2)*133 + ha] = dup2(va.z);
            Ad[(cq*4+3)*133 + ha] = dup2(va.w);
            *(float4*)(Bd + kb*132 + t4*4) = vb;
        }
        __syncthreads();

        for (int s = 0; s < 10; s++) {
            const int buf = s & 1;
            const bool more = (s + 1 < 10);
            if (more) {
                int k0 = (s + 1) * 16;
                int c  = k0 + cq * 4;
                va = (c < CIN) ? *(const float4*)(Wr + c) : make_float4(0.f,0.f,0.f,0.f);
                int ck = k0 + kb;
                vb = (ck < CIN) ? *(const float4*)(Xb + (size_t)ck * TT + t0 + t4 * 4)
                                : make_float4(0.f,0.f,0.f,0.f);
            }
            const ull*   Ab = Asd + buf * (16*133);
            const float* Bb = Bsf + buf * (16*132);
#pragma unroll
            for (int k = 0; k < 16; k++) {
                const ull* Ar = Ab + k * 133 + ty * 8;
                ull a0 = Ar[0], a1 = Ar[1], a2 = Ar[2], a3 = Ar[3];
                ull a4 = Ar[4], a5 = Ar[5], a6 = Ar[6], a7 = Ar[7];
                ulonglong2 bb = *((const ulonglong2*)(Bb + k * 132) + tx);
                ffma2(acc[0][0], a0, bb.x); ffma2(acc[0][1], a0, bb.y);
                ffma2(acc[1][0], a1, bb.x); ffma2(acc[1][1], a1, bb.y);
                ffma2(acc[2][0], a2, bb.x); ffma2(acc[2][1], a2, bb.y);
                ffma2(acc[3][0], a3, bb.x); ffma2(acc[3][1], a3, bb.y);
                ffma2(acc[4][0], a4, bb.x); ffma2(acc[4][1], a4, bb.y);
                ffma2(acc[5][0], a5, bb.x); ffma2(acc[5][1], a5, bb.y);
                ffma2(acc[6][0], a6, bb.x); ffma2(acc[6][1], a6, bb.y);
                ffma2(acc[7][0], a7, bb.x); ffma2(acc[7][1], a7, bb.y);
            }
            if (more) {
                ull* Ad = Asd + (buf ^ 1) * (16*133);
                float* Bd = Bsf + (buf ^ 1) * (16*132);
                Ad[(cq*4+0)*133 + ha] = dup2(va.x);
                Ad[(cq*4+1)*133 + ha] = dup2(va.y);
                Ad[(cq*4+2)*133 + ha] = dup2(va.z);
                Ad[(cq*4+3)*133 + ha] = dup2(va.w);
                *(float4*)(Bd + kb*132 + t4*4) = vb;
                __syncthreads();
            }
        }

        // epilogue: acc -> Ct[h][t]
#pragma unroll
        for (int i = 0; i < 8; i++) {
#pragma unroll
            for (int j = 0; j < 2; j++) {
                float2 f = *(float2*)&acc[i][j];
                *(float2*)(Ct + (ty*8 + i)*132 + tx*4 + 2*j) = f;
            }
        }
        __syncthreads();

        // fused psp scan + spike
        if (tid < 128) {
            float y = ycar;
            const float* row = Ct + tid * 132;
            unsigned* orow = (unsigned*)(Cu8 + tid * 132);
#pragma unroll 4
            for (int q = 0; q < 32; q++) {
                float4 v = *(const float4*)(row + q * 4);
                unsigned pk;
                y = fmaf(ALPHA_F, y, v.x); pk  = (y >= THETA_F) ? 1u : 0u;
                y = fmaf(ALPHA_F, y, v.y); pk |= (y >= THETA_F) ? (1u<<8) : 0u;
                y = fmaf(ALPHA_F, y, v.z); pk |= (y >= THETA_F) ? (1u<<16) : 0u;
                y = fmaf(ALPHA_F, y, v.w); pk |= (y >= THETA_F) ? (1u<<24) : 0u;
                orow[q] = pk;
            }
            ycar = y;
        }
        __syncthreads();

        // coalesced u8 copy-out
        unsigned char* dstb = g_s1u8 + ((size_t)b * HID + h0) * TT + t0;
#pragma unroll
        for (int it = 0; it < 8; it++) {
            int idx = tid + 512 * it;
            int row = idx >> 5, q = idx & 31;
            unsigned v = *(const unsigned*)(Cu8 + row * 132 + q * 4);
            *(unsigned*)(dstb + (size_t)row * TT + q * 4) = v;
        }
        __syncthreads();
    }
}

// ===========================================================================
// FUSED branch2 layer1 + psp + spike — 512 threads, microtile 4h x 10c.
//   l1a[b,h,c] = sum_t Wl1[h,t]*X[b,perm[c],t] (t ascending 0..2047)
//   scan over c; spikes (f32) -> g_l1[b][c][h].
// Thread: tx=tid&15 -> c-pairs {tx+16q}, q=0..4 ; ty=tid>>4 (0..31) -> 4 h.
// Same per-output reduction order as before (k ascending, single chain).
// smem: Asd ull[2][16*130] @0 (33280) | Bsd ull[2][16*81] @33280 (20736)
//       Ct f32[128][162] @54016 (82944) | prow @136960  total 137600
// ===========================================================================
#define B2_SMEM 137600

__global__ __launch_bounds__(512) void k_b2l1_psp(const float* __restrict__ X,
                                                  const float* __restrict__ Wl1,
                                                  const int* __restrict__ perm) {
    extern __shared__ char sm[];
    ull*   Asd = (ull*)sm;                        // [2][16*130]
    ull*   Bsd = (ull*)(sm + 33280);              // [2][16*81]
    float* Ct  = (float*)(sm + 54016);            // [128][162]
    int*   prow = (int*)(sm + 136960);

    const int b  = blockIdx.y;
    const int h0 = blockIdx.x * 128;
    const int tid = threadIdx.x;
    const int tx = tid & 15, ty = tid >> 4;       // ty 0..31
    const int ha = tid >> 2, kqa = tid & 3;       // A fill: h=ha, k=kqa*4..+3
    const float* Xb = X + (size_t)b * CIN * TT;
    const float* Wr = Wl1 + (size_t)(h0 + ha) * TT + kqa * 4;

    if (tid < 160) prow[tid] = (tid < CIN) ? perm[tid] : 0;
    __syncthreads();

    ull acc[4][5];
#pragma unroll
    for (int i = 0; i < 4; i++)
#pragma unroll
        for (int q = 0; q < 5; q++) acc[i][q] = 0ULL;

    // B fill: 640 (c,kq) items, idx = tid + 512*it, it=0..1 (2nd masked)
    float4 va, vb[2];

    // ---- prologue: slab 0 loads ----
    va = *(const float4*)(Wr);
#pragma unroll
    for (int it = 0; it < 2; it++) {
        int idx = tid + 512 * it;
        if (idx < 640) {
            int c = idx >> 2, kq = idx & 3;
            vb[it] = *(const float4*)(Xb + (size_t)prow[c] * TT + kq * 4);
        }
    }
    // ---- prologue: slab 0 stores ----
    {
        ull* Ad = Asd;
        int kb = kqa * 4;
        Ad[(kb+0)*130 + ha] = dup2(va.x);
        Ad[(kb+1)*130 + ha] = dup2(va.y);
        Ad[(kb+2)*130 + ha] = dup2(va.z);
        Ad[(kb+3)*130 + ha] = dup2(va.w);
#pragma unroll
        for (int it = 0; it < 2; it++) {
            int idx = tid + 512 * it;
            if (idx < 640) {
                int c = idx >> 2, kq = idx & 3;
                int p = c >> 1, hf = c & 1;
                ((float*)(Bsd + (size_t)(kq*4+0)*81 + p))[hf] = vb[it].x;
                ((float*)(Bsd + (size_t)(kq*4+1)*81 + p))[hf] = vb[it].y;
                ((float*)(Bsd + (size_t)(kq*4+2)*81 + p))[hf] = vb[it].z;
                ((float*)(Bsd + (size_t)(kq*4+3)*81 + p))[hf] = vb[it].w;
            }
        }
    }
    __syncthreads();

    for (int s = 0; s < TT / 16; s++) {
        const int buf = s & 1;
        const bool more = (s + 1 < TT / 16);
        if (more) {
            int k0 = (s + 1) * 16;
            va = *(const float4*)(Wr + k0);
#pragma unroll
            for (int it = 0; it < 2; it++) {
                int idx = tid + 512 * it;
                if (idx < 640) {
                    int c = idx >> 2, kq = idx & 3;
                    vb[it] = *(const float4*)(Xb + (size_t)prow[c] * TT + k0 + kq * 4);
                }
            }
        }
        const ull* Ab = Asd + buf * (16*130);
        const ull* Bb = Bsd + buf * (16*81);
#pragma unroll
        for (int k = 0; k < 16; k++) {
            const ull* Ar = Ab + k * 130 + ty * 4;
            ull a0 = Ar[0], a1 = Ar[1], a2 = Ar[2], a3 = Ar[3];
            const ull* Br = Bb + k * 81;
            ull b0 = Br[tx], b1 = Br[tx+16], b2 = Br[tx+32],
                b3 = Br[tx+48], b4 = Br[tx+64];
            ffma2(acc[0][0], a0, b0); ffma2(acc[1][0], a1, b0);
            ffma2(acc[2][0], a2, b0); ffma2(acc[3][0], a3, b0);
            ffma2(acc[0][1], a0, b1); ffma2(acc[1][1], a1, b1);
            ffma2(acc[2][1], a2, b1); ffma2(acc[3][1], a3, b1);
            ffma2(acc[0][2], a0, b2); ffma2(acc[1][2], a1, b2);
            ffma2(acc[2][2], a2, b2); ffma2(acc[3][2], a3, b2);
            ffma2(acc[0][3], a0, b3); ffma2(acc[1][3], a1, b3);
            ffma2(acc[2][3], a2, b3); ffma2(acc[3][3], a3, b3);
            ffma2(acc[0][4], a0, b4); ffma2(acc[1][4], a1, b4);
            ffma2(acc[2][4], a2, b4); ffma2(acc[3][4], a3, b4);
        }
        if (more) {
            ull* Ad = Asd + (buf ^ 1) * (16*130);
            ull* Bd = Bsd + (buf ^ 1) * (16*81);
            int kb = kqa * 4;
            Ad[(kb+0)*130 + ha] = dup2(va.x);
            Ad[(kb+1)*130 + ha] = dup2(va.y);
            Ad[(kb+2)*130 + ha] = dup2(va.z);
            Ad[(kb+3)*130 + ha] = dup2(va.w);
#pragma unroll
            for (int it = 0; it < 2; it++) {
                int idx = tid + 512 * it;
                if (idx < 640) {
                    int c = idx >> 2, kq = idx & 3;
                    int p = c >> 1, hf = c & 1;
                    ((float*)(Bd + (size_t)(kq*4+0)*81 + p))[hf] = vb[it].x;
                    ((float*)(Bd + (size_t)(kq*4+1)*81 + p))[hf] = vb[it].y;
                    ((float*)(Bd + (size_t)(kq*4+2)*81 + p))[hf] = vb[it].z;
                    ((float*)(Bd + (size_t)(kq*4+3)*81 + p))[hf] = vb[it].w;
                }
            }
            __syncthreads();
        }
    }

    // ---- epilogue: acc (pairs over c at p = tx+16q) -> Ct[h][c] ----
    __syncthreads();
#pragma unroll
    for (int i = 0; i < 4; i++)
#pragma unroll
        for (int q = 0; q < 5; q++) {
            float2 f = *(float2*)&acc[i][q];
            int p = tx + 16 * q;
            *(float2*)(Ct + (ty*4 + i)*162 + 2*p) = f;
        }
    __syncthreads();

    // ---- fused psp scan over c + spike (in-place float) ----
    if (tid < 128) {
        float y = 0.0f;
        float* row = Ct + tid * 162;
#pragma unroll 4
        for (int c = 0; c < CIN; c++) {
            y = fmaf(ALPHA_F, y, row[c]);
            row[c] = (y >= THETA_F) ? 1.0f : 0.0f;
        }
    }
    __syncthreads();

    // ---- coalesced store to g_l1[b][c][h0..h0+127] ----
    float* dstb = g_l1 + (size_t)b * CIN * HID + h0;
    for (int idx = tid; idx < CIN * 128; idx += 512) {
        int c = idx >> 7, hh = idx & 127;
        dstb[(size_t)c * HID + hh] = Ct[hh * 162 + c];
    }
}

// ===========================================================================
// Branch1 layer2: a2[b,o,t] = sum_h W2[o,h] * s1u8[b,h,t]  (unchanged)
// ===========================================================================
__global__ __launch_bounds__(256) void k_gemm_b1l2(const float* __restrict__ W2) {
    __shared__ ull   Wsd[2][32 * 21];
    __shared__ float Ssf[2][32 * 132];

    const int b  = blockIdx.y;
    const int t0 = blockIdx.x * 128;
    const int tid = threadIdx.x;
    const int tx = tid & 63, ty = tid >> 6;
    const unsigned char* Sb = g_s1u8 + (size_t)b * HID * TT + t0;

    ull acc[5];
#pragma unroll
    for (int q = 0; q < 5; q++) acc[q] = 0ULL;

    float vwf[3];  uchar4 vu[4];

#pragma unroll
    for (int it = 0; it < 3; it++) {
        int idx = tid + 256 * it;
        if (idx < 640) vwf[it] = W2[(idx >> 5) * HID + (idx & 31)];
    }
#pragma unroll
    for (int it = 0; it < 4; it++) {
        int idx = tid + 256 * it;
        vu[it] = *(const uchar4*)(Sb + (size_t)(idx >> 5) * TT + (idx & 31) * 4);
    }
    {
#pragma unroll
        for (int it = 0; it < 3; it++) {
            int idx = tid + 256 * it;
            if (idx < 640) Wsd[0][(idx & 31) * 21 + (idx >> 5)] = dup2(vwf[it]);
        }
#pragma unroll
        for (int it = 0; it < 4; it++) {
            int idx = tid + 256 * it;
            *(float4*)&Ssf[0][(idx >> 5) * 132 + (idx & 31) * 4] =
                make_float4((float)vu[it].x, (float)vu[it].y,
                            (float)vu[it].z, (float)vu[it].w);
        }
    }
    __syncthreads();

    for (int s = 0; s < HID / 32; s++) {
        const int buf = s & 1;
        const bool more = (s + 1 < HID / 32);
        if (more) {
            int k0 = (s + 1) * 32;
#pragma unroll
            for (int it = 0; it < 3; it++) {
                int idx = tid + 256 * it;
                if (idx < 640) vwf[it] = W2[(idx >> 5) * HID + k0 + (idx & 31)];
            }
#pragma unroll
            for (int it = 0; it < 4; it++) {
                int idx = tid + 256 * it;
                vu[it] = *(const uchar4*)(Sb + (size_t)(k0 + (idx >> 5)) * TT
                                             + (idx & 31) * 4);
            }
        }
#pragma unroll
        for (int k = 0; k < 32; k++) {
            const ull* Ar = &Wsd[buf][k * 21 + ty * 5];
            ull a0 = Ar[0], a1 = Ar[1], a2 = Ar[2], a3 = Ar[3], a4 = Ar[4];
            ull bv = *((const ull*)&Ssf[buf][k * 132] + tx);
            ffma2(acc[0], a0, bv);
            ffma2(acc[1], a1, bv);
            ffma2(acc[2], a2, bv);
            ffma2(acc[3], a3, bv);
            ffma2(acc[4], a4, bv);
        }
        if (more) {
#pragma unroll
            for (int it = 0; it < 3; it++) {
                int idx = tid + 256 * it;
                if (idx < 640) Wsd[buf^1][(idx & 31) * 21 + (idx >> 5)] = dup2(vwf[it]);
            }
#pragma unroll
            for (int it = 0; it < 4; it++) {
                int idx = tid + 256 * it;
                *(float4*)&Ssf[buf^1][(idx >> 5) * 132 + (idx & 31) * 4] =
                    make_float4((float)vu[it].x, (float)vu[it].y,
                                (float)vu[it].z, (float)vu[it].w);
            }
            __syncthreads();
        }
    }

#pragma unroll
    for (int q = 0; q < 5; q++) {
        int o = ty * 5 + q;
        *(ull*)(g_a2 + ((size_t)b * NOUT + o) * TT + t0 + tx * 2) = acc[q];
    }
}

// ---------------------------------------------------------------------------
// Warp-per-row output scans (unchanged)
// ---------------------------------------------------------------------------
__device__ __forceinline__ void scan_rows(const float* __restrict__ in,
                                          float* __restrict__ out,
                                          int len, int out_off) {
    __shared__ float4 buf[8][32];
    const int w = threadIdx.x >> 5, lane = threadIdx.x & 31;
    const int row = blockIdx.x * 8 + w;
    const float* ip = in + (size_t)row * len;
    float* op = out + (size_t)row * OUTT + out_off;
    const int nch = (len + 127) / 128;

    float y = 0.0f;
    int idx = lane * 4;
    float4 v = make_float4(0.f, 0.f, 0.f, 0.f);
    if (idx < len) v = *(const float4*)(ip + idx);

    for (int ch = 0; ch < nch; ch++) {
        buf[w][lane] = v;
        __syncwarp();
        int nidx = (ch + 1) * 128 + lane * 4;
        if (nidx < len) v = *(const float4*)(ip + nidx);
        if (lane == 0) {
            int n4 = (len - ch * 128) >> 2; if (n4 > 32) n4 = 32;
            for (int i = 0; i < n4; i++) {
                float4 u = buf[w][i]; float4 s;
                y = fmaf(ALPHA_F, y, u.x); s.x = (y >= THETA_F) ? 1.0f : 0.0f;
                y = fmaf(ALPHA_F, y, u.y); s.y = (y >= THETA_F) ? 1.0f : 0.0f;
                y = fmaf(ALPHA_F, y, u.z); s.z = (y >= THETA_F) ? 1.0f : 0.0f;
                y = fmaf(ALPHA_F, y, u.w); s.w = (y >= THETA_F) ? 1.0f : 0.0f;
                buf[w][i] = s;
            }
        }
        __syncwarp();
        int oi = ch * 128 + lane * 4;
        if (oi < len) *(float4*)(op + oi) = buf[w][lane];
        __syncwarp();
    }
}

__global__ __launch_bounds__(256) void k_scan_a2(float* __restrict__ out) {
    scan_rows(g_a2, out, TT, 0);
}
__global__ __launch_bounds__(256) void k_scan_l2(float* __restrict__ out) {
    scan_rows(g_l2, out, CIN, TT);
}

// ---------------------------------------------------------------------------
// Branch2 layer2: l2[b,o,c] = sum_h Wl2[o,h] * l1[b,c,h]  (unchanged)
// ---------------------------------------------------------------------------
__global__ __launch_bounds__(160) void k_gemm_b2l2(const float* __restrict__ Wl2) {
    __shared__ float Ws[4 * HID];
    const int og = blockIdx.x;
    const int b  = blockIdx.y;
    const int tid = threadIdx.x;

    for (int idx = tid; idx < 4 * HID; idx += 160)
        Ws[idx] = Wl2[(og * 4 + (idx >> 9)) * HID + (idx & (HID - 1))];
    __syncthreads();

    const int c = tid;
    if (c >= CIN) return;
    const float* Lb = g_l1 + ((size_t)b * CIN + c) * HID;
    float acc[4] = {0.f, 0.f, 0.f, 0.f};

#pragma unroll 4
    for (int h = 0; h < HID; h += 4) {
        float4 xv = *(const float4*)(Lb + h);
#pragma unroll
        for (int o = 0; o < 4; o++) {
            const float4 w = *(const float4*)&Ws[o * HID + h];
            acc[o] = fmaf(w.x, xv.x, acc[o]);
            acc[o] = fmaf(w.y, xv.y, acc[o]);
            acc[o] = fmaf(w.z, xv.z, acc[o]);
            acc[o] = fmaf(w.w, xv.w, acc[o]);
        }
    }
#pragma unroll
    for (int o = 0; o < 4; o++)
        g_l2[((size_t)b * NOUT + og * 4 + o) * CIN + c] = acc[o];
}

// ---------------------------------------------------------------------------
// Launch: fork branch-2 onto a secondary stream, join before return.
// All device work per call is identical; streams/events are created once
// (host-side resources only — no device memory involved).
// ---------------------------------------------------------------------------
extern "C" void kernel_launch(void* const* d_in, const int* in_sizes, int n_in,
                              void* d_out, int out_size) {
    (void)in_sizes; (void)n_in; (void)out_size;
    const float* X    = (const float*)d_in[0];
    const float* W1   = (const float*)d_in[1];
    const float* W2   = (const float*)d_in[2];
    const float* Wl1  = (const float*)d_in[3];
    const float* Wl2  = (const float*)d_in[4];
    const int*   perm = (const int*)d_in[5];
    float* out = (float*)d_out;

    static cudaStream_t s2 = [] {
        cudaStream_t s; cudaStreamCreateWithFlags(&s, cudaStreamNonBlocking); return s;
    }();
    static cudaEvent_t evFork = [] {
        cudaEvent_t e; cudaEventCreateWithFlags(&e, cudaEventDisableTiming); return e;
    }();
    static cudaEvent_t evJoin = [] {
        cudaEvent_t e; cudaEventCreateWithFlags(&e, cudaEventDisableTiming); return e;
    }();

    cudaFuncSetAttribute(k_b1l1_psp, cudaFuncAttributeMaxDynamicSharedMemorySize, B1_SMEM);
    cudaFuncSetAttribute(k_b2l1_psp, cudaFuncAttributeMaxDynamicSharedMemorySize, B2_SMEM);

    // fork: branch 2 on s2, dependent on everything upstream on the main stream
    cudaEventRecord(evFork, 0);
    cudaStreamWaitEvent(s2, evFork, 0);
    k_b2l1_psp<<<dim3(HID / 128, BB), 512, B2_SMEM, s2>>>(X, Wl1, perm);
    k_gemm_b2l2<<<dim3(5, BB), 160, 0, s2>>>(Wl2);
    k_scan_l2<<<BB * NOUT / 8, 256, 0, s2>>>(out);
    cudaEventRecord(evJoin, s2);

    // branch 1 on the main stream
    k_b1l1_psp<<<dim3(HID / 128, BB), 512, B1_SMEM>>>(X, W1);
    k_gemm_b1l2<<<dim3(TT / 128, BB), 256>>>(W2);
    k_scan_a2<<<BB * NOUT / 8, 256>>>(out);

    // join
    cudaStreamWaitEvent(0, evJoin, 0);
}

// round 12
// speedup vs baseline: 1.0692x; 1.0692x over previous
#include <cuda_runtime.h>
#include <cstdint>

// SLAYER constants
#define ALPHA_F 0.90483741803595952f
#define THETA_F 10.0f

// Problem dims
#define BB   32
#define CIN  156
#define TT   2048
#define HID  512
#define NOUT 20
#define OUTT (TT + CIN)   // 2204

typedef unsigned long long ull;

// ---------------------------------------------------------------------------
// Scratch
// ---------------------------------------------------------------------------
__device__ unsigned char g_s1u8[(size_t)BB * HID * TT];  // branch1 layer1 spikes (u8)
__device__ float         g_a2[(size_t)BB * NOUT * TT];   // branch1 layer2 pre-acts
__device__ float         g_l1[(size_t)BB * CIN * HID];   // branch2 spikes, [b][c][h]
__device__ float         g_l2[(size_t)BB * NOUT * CIN];  // branch2 layer2 pre-acts

// packed fp32x2 FMA: two independent rn-rounded fp32 FMAs (bitwise == scalar fmaf)
__device__ __forceinline__ void ffma2(ull& d, ull a, ull b) {
    asm("fma.rn.f32x2 %0, %1, %2, %0;" : "+l"(d) : "l"(a), "l"(b));
}
__device__ __forceinline__ ull dup2(float v) {
    float2 f = make_float2(v, v);
    return *(ull*)&f;
}

// ===========================================================================
// FUSED branch1 layer1 + psp + spike.
//   a1[b,h,t] = sum_c W1[h,c]*X[b,c,t] (c ascending 0..159, zero-padded)
//   y[t] = alpha*y[t-1] + a1[t]; spike -> u8 g_s1u8.
// Block (h0 of 64, b) = grid (8,32)=256, 256 threads, 16 t-tiles of 128,
// BK=16 double-buffered. A dup pairs stride 66 (16B-aligned -> LDS.128 x4),
// B natural pairs (1 LDS.128). Thread: tx=tid&31 -> 4t, ty=tid>>5 -> 8h.
// smem: Asd ull[2][16*66] @0 (16896) | Bsf f32[2][16*132] @16896 (16896)
//       Ct f32[64][132] @33792 (33792) | Cu8 u8[64][132] @67584 (8448)
//       total 76032 -> 2 blocks/SM
// ===========================================================================
#define B1_SMEM 76032

__global__ __launch_bounds__(256) void k_b1l1_psp(const float* __restrict__ X,
                                                  const float* __restrict__ W1) {
    extern __shared__ char sm[];
    ull*   Asd = (ull*)sm;                         // [2][16*66]
    float* Bsf = (float*)(sm + 16896);             // [2][16*132]
    float* Ct  = (float*)(sm + 33792);             // [64][132]
    unsigned char* Cu8 = (unsigned char*)(sm + 67584);

    const int b  = blockIdx.y;
    const int h0 = blockIdx.x * 64;
    const int tid = threadIdx.x;
    const int tx = tid & 31, ty = tid >> 5;        // ty 0..7 (8h each)
    const int ha = tid >> 2, cq = tid & 3;         // A-fill: h=ha(0..63), c-quad
    const float* Xb = X + (size_t)b * CIN * TT;
    const float* Wr = W1 + (size_t)(h0 + ha) * CIN;

    float ycar = 0.0f;                             // psp carry (threads 0..63)

    for (int t0 = 0; t0 < TT; t0 += 128) {
        ull acc[8][2];
#pragma unroll
        for (int i = 0; i < 8; i++) { acc[i][0] = 0ULL; acc[i][1] = 0ULL; }

        // ---- prologue: slab 0 (k0 = 0) ----
        float4 va, vb[2];
        {
            int c = cq * 4;
            va = (c < CIN) ? *(const float4*)(Wr + c) : make_float4(0.f,0.f,0.f,0.f);
#pragma unroll
            for (int it = 0; it < 2; it++) {
                int slot = tid + 256 * it;         // 0..511
                int kb = slot >> 5, t4 = slot & 31;
                vb[it] = (kb < CIN)
                       ? *(const float4*)(Xb + (size_t)kb * TT + t0 + t4 * 4)
                       : make_float4(0.f,0.f,0.f,0.f);
            }
        }
        {
            ull* Ad = Asd;  float* Bd = Bsf;
            Ad[(cq*4+0)*66 + ha] = dup2(va.x);
            Ad[(cq*4+1)*66 + ha] = dup2(va.y);
            Ad[(cq*4+2)*66 + ha] = dup2(va.z);
            Ad[(cq*4+3)*66 + ha] = dup2(va.w);
#pragma unroll
            for (int it = 0; it < 2; it++) {
                int slot = tid + 256 * it;
                int kb = slot >> 5, t4 = slot & 31;
                *(float4*)(Bd + kb*132 + t4*4) = vb[it];
            }
        }
        __syncthreads();

        for (int s = 0; s < 10; s++) {
            const int buf = s & 1;
            const bool more = (s + 1 < 10);
            if (more) {
                int k0 = (s + 1) * 16;
                int c  = k0 + cq * 4;
                va = (c < CIN) ? *(const float4*)(Wr + c) : make_float4(0.f,0.f,0.f,0.f);
#pragma unroll
                for (int it = 0; it < 2; it++) {
                    int slot = tid + 256 * it;
                    int kb = slot >> 5, t4 = slot & 31;
                    int ck = k0 + kb;
                    vb[it] = (ck < CIN)
                           ? *(const float4*)(Xb + (size_t)ck * TT + t0 + t4 * 4)
                           : make_float4(0.f,0.f,0.f,0.f);
                }
            }
            const ull*   Ab = Asd + buf * (16*66);
            const float* Bb = Bsf + buf * (16*132);
#pragma unroll
            for (int k = 0; k < 16; k++) {
                const ull* Ar = Ab + k * 66 + ty * 8;
                ulonglong2 a01 = *(const ulonglong2*)(Ar);
                ulonglong2 a23 = *(const ulonglong2*)(Ar + 2);
                ulonglong2 a45 = *(const ulonglong2*)(Ar + 4);
                ulonglong2 a67 = *(const ulonglong2*)(Ar + 6);
                ulonglong2 bb = *((const ulonglong2*)(Bb + k * 132) + tx);
                ffma2(acc[0][0], a01.x, bb.x); ffma2(acc[0][1], a01.x, bb.y);
                ffma2(acc[1][0], a01.y, bb.x); ffma2(acc[1][1], a01.y, bb.y);
                ffma2(acc[2][0], a23.x, bb.x); ffma2(acc[2][1], a23.x, bb.y);
                ffma2(acc[3][0], a23.y, bb.x); ffma2(acc[3][1], a23.y, bb.y);
                ffma2(acc[4][0], a45.x, bb.x); ffma2(acc[4][1], a45.x, bb.y);
                ffma2(acc[5][0], a45.y, bb.x); ffma2(acc[5][1], a45.y, bb.y);
                ffma2(acc[6][0], a67.x, bb.x); ffma2(acc[6][1], a67.x, bb.y);
                ffma2(acc[7][0], a67.y, bb.x); ffma2(acc[7][1], a67.y, bb.y);
            }
            if (more) {
                ull* Ad = Asd + (buf ^ 1) * (16*66);
                float* Bd = Bsf + (buf ^ 1) * (16*132);
                Ad[(cq*4+0)*66 + ha] = dup2(va.x);
                Ad[(cq*4+1)*66 + ha] = dup2(va.y);
                Ad[(cq*4+2)*66 + ha] = dup2(va.z);
                Ad[(cq*4+3)*66 + ha] = dup2(va.w);
#pragma unroll
                for (int it = 0; it < 2; it++) {
                    int slot = tid + 256 * it;
                    int kb = slot >> 5, t4 = slot & 31;
                    *(float4*)(Bd + kb*132 + t4*4) = vb[it];
                }
                __syncthreads();
            }
        }

        // ---- epilogue: acc -> Ct[h][t] (pairs natural over t) ----
#pragma unroll
        for (int i = 0; i < 8; i++) {
#pragma unroll
            for (int j = 0; j < 2; j++) {
                float2 f = *(float2*)&acc[i][j];
                *(float2*)(Ct + (ty*8 + i)*132 + tx*4 + 2*j) = f;
            }
        }
        __syncthreads();

        // ---- fused psp scan + spike (threads 0..63) ----
        if (tid < 64) {
            float y = ycar;
            const float* row = Ct + tid * 132;
            unsigned* orow = (unsigned*)(Cu8 + tid * 132);
#pragma unroll 4
            for (int q = 0; q < 32; q++) {
                float4 v = *(const float4*)(row + q * 4);
                unsigned pk;
                y = fmaf(ALPHA_F, y, v.x); pk  = (y >= THETA_F) ? 1u : 0u;
                y = fmaf(ALPHA_F, y, v.y); pk |= (y >= THETA_F) ? (1u<<8) : 0u;
                y = fmaf(ALPHA_F, y, v.z); pk |= (y >= THETA_F) ? (1u<<16) : 0u;
                y = fmaf(ALPHA_F, y, v.w); pk |= (y >= THETA_F) ? (1u<<24) : 0u;
                orow[q] = pk;
            }
            ycar = y;
        }
        __syncthreads();

        // ---- coalesced u8 copy-out (64 rows x 128 t) ----
        unsigned char* dstb = g_s1u8 + ((size_t)b * HID + h0) * TT + t0;
#pragma unroll
        for (int it = 0; it < 8; it++) {
            int idx = tid + 256 * it;          // 0..2047
            int row = idx >> 5, q = idx & 31;
            unsigned v = *(const unsigned*)(Cu8 + row * 132 + q * 4);
            *(unsigned*)(dstb + (size_t)row * TT + q * 4) = v;
        }
        __syncthreads();
    }
}

// ===========================================================================
// FUSED branch2 layer1 + psp + spike.
//   l1a[b,h,c] = sum_t Wl1[h,t]*X[b,perm[c],t] (t ascending 0..2047)
//   scan over c; spikes (f32) -> g_l1[b][c][h].
// Block (h0 of 64, b) = grid (8,32)=256, 256 threads, BK=16 double-buffered.
// Thread: tx=tid&15 -> c-pairs {tx+16q} q=0..4; ty=tid>>4 (0..15) -> 4h.
// smem: Asd ull[2][16*66] @0 (16896) | Bsd ull[2][16*81] @16896 (20736)
//       Ct f32[64][162] @37632 (41472) | prow @79104 (640)  total 79744
// ===========================================================================
#define B2_SMEM 79744

__global__ __launch_bounds__(256) void k_b2l1_psp(const float* __restrict__ X,
                                                  const float* __restrict__ Wl1,
                                                  const int* __restrict__ perm) {
    extern __shared__ char sm[];
    ull*   Asd = (ull*)sm;                        // [2][16*66]
    ull*   Bsd = (ull*)(sm + 16896);              // [2][16*81]
    float* Ct  = (float*)(sm + 37632);            // [64][162]
    int*   prow = (int*)(sm + 79104);

    const int b  = blockIdx.y;
    const int h0 = blockIdx.x * 64;
    const int tid = threadIdx.x;
    const int tx = tid & 15, ty = tid >> 4;       // ty 0..15 (4h each)
    const int ha = tid >> 2, kqa = tid & 3;       // A fill: h=ha(0..63), k=kqa*4..+3
    const float* Xb = X + (size_t)b * CIN * TT;
    const float* Wr = Wl1 + (size_t)(h0 + ha) * TT + kqa * 4;

    if (tid < 160) prow[tid] = (tid < CIN) ? perm[tid] : 0;
    __syncthreads();

    ull acc[4][5];
#pragma unroll
    for (int i = 0; i < 4; i++)
#pragma unroll
        for (int q = 0; q < 5; q++) acc[i][q] = 0ULL;

    // B fill: 640 (c,kq) float4 slots; idx = tid + 256*it, it=0..2 (3rd masked)
    float4 va, vb[3];

    // ---- prologue: slab 0 ----
    va = *(const float4*)(Wr);
#pragma unroll
    for (int it = 0; it < 3; it++) {
        int idx = tid + 256 * it;
        if (idx < 640) {
            int c = idx >> 2, kq = idx & 3;
            vb[it] = *(const float4*)(Xb + (size_t)prow[c] * TT + kq * 4);
        }
    }
    {
        ull* Ad = Asd;
        int kb = kqa * 4;
        Ad[(kb+0)*66 + ha] = dup2(va.x);
        Ad[(kb+1)*66 + ha] = dup2(va.y);
        Ad[(kb+2)*66 + ha] = dup2(va.z);
        Ad[(kb+3)*66 + ha] = dup2(va.w);
#pragma unroll
        for (int it = 0; it < 3; it++) {
            int idx = tid + 256 * it;
            if (idx < 640) {
                int c = idx >> 2, kq = idx & 3;
                int p = c >> 1, hf = c & 1;
                ((float*)(Bsd + (size_t)(kq*4+0)*81 + p))[hf] = vb[it].x;
                ((float*)(Bsd + (size_t)(kq*4+1)*81 + p))[hf] = vb[it].y;
                ((float*)(Bsd + (size_t)(kq*4+2)*81 + p))[hf] = vb[it].z;
                ((float*)(Bsd + (size_t)(kq*4+3)*81 + p))[hf] = vb[it].w;
            }
        }
    }
    __syncthreads();

    for (int s = 0; s < TT / 16; s++) {
        const int buf = s & 1;
        const bool more = (s + 1 < TT / 16);
        if (more) {
            int k0 = (s + 1) * 16;
            va = *(const float4*)(Wr + k0);
#pragma unroll
            for (int it = 0; it < 3; it++) {
                int idx = tid + 256 * it;
                if (idx < 640) {
                    int c = idx >> 2, kq = idx & 3;
                    vb[it] = *(const float4*)(Xb + (size_t)prow[c] * TT + k0 + kq * 4);
                }
            }
        }
        const ull* Ab = Asd + buf * (16*66);
        const ull* Bb = Bsd + buf * (16*81);
#pragma unroll
        for (int k = 0; k < 16; k++) {
            const ull* Ar = Ab + k * 66 + ty * 4;
            ulonglong2 a01 = *(const ulonglong2*)(Ar);
            ulonglong2 a23 = *(const ulonglong2*)(Ar + 2);
            ull a0 = a01.x, a1 = a01.y, a2 = a23.x, a3 = a23.y;
            const ull* Br = Bb + k * 81;
            ull b0 = Br[tx], b1 = Br[tx+16], b2 = Br[tx+32],
                b3 = Br[tx+48], b4 = Br[tx+64];
            ffma2(acc[0][0], a0, b0); ffma2(acc[1][0], a1, b0);
            ffma2(acc[2][0], a2, b0); ffma2(acc[3][0], a3, b0);
            ffma2(acc[0][1], a0, b1); ffma2(acc[1][1], a1, b1);
            ffma2(acc[2][1], a2, b1); ffma2(acc[3][1], a3, b1);
            ffma2(acc[0][2], a0, b2); ffma2(acc[1][2], a1, b2);
            ffma2(acc[2][2], a2, b2); ffma2(acc[3][2], a3, b2);
            ffma2(acc[0][3], a0, b3); ffma2(acc[1][3], a1, b3);
            ffma2(acc[2][3], a2, b3); ffma2(acc[3][3], a3, b3);
            ffma2(acc[0][4], a0, b4); ffma2(acc[1][4], a1, b4);
            ffma2(acc[2][4], a2, b4); ffma2(acc[3][4], a3, b4);
        }
        if (more) {
            ull* Ad = Asd + (buf ^ 1) * (16*66);
            ull* Bd = Bsd + (buf ^ 1) * (16*81);
            int kb = kqa * 4;
            Ad[(kb+0)*66 + ha] = dup2(va.x);
            Ad[(kb+1)*66 + ha] = dup2(va.y);
            Ad[(kb+2)*66 + ha] = dup2(va.z);
            Ad[(kb+3)*66 + ha] = dup2(va.w);
#pragma unroll
            for (int it = 0; it < 3; it++) {
                int idx = tid + 256 * it;
                if (idx < 640) {
                    int c = idx >> 2, kq = idx & 3;
                    int p = c >> 1, hf = c & 1;
                    ((float*)(Bd + (size_t)(kq*4+0)*81 + p))[hf] = vb[it].x;
                    ((float*)(Bd + (size_t)(kq*4+1)*81 + p))[hf] = vb[it].y;
                    ((float*)(Bd + (size_t)(kq*4+2)*81 + p))[hf] = vb[it].z;
                    ((float*)(Bd + (size_t)(kq*4+3)*81 + p))[hf] = vb[it].w;
                }
            }
            __syncthreads();
        }
    }

    // ---- epilogue: acc (pairs over c at p = tx+16q) -> Ct[h][c] ----
    __syncthreads();
#pragma unroll
    for (int i = 0; i < 4; i++)
#pragma unroll
        for (int q = 0; q < 5; q++) {
            float2 f = *(float2*)&acc[i][q];
            int p = tx + 16 * q;
            *(float2*)(Ct + (ty*4 + i)*162 + 2*p) = f;
        }
    __syncthreads();

    // ---- fused psp scan over c + spike (threads 0..63, in-place) ----
    if (tid < 64) {
        float y = 0.0f;
        float* row = Ct + tid * 162;
#pragma unroll 4
        for (int c = 0; c < CIN; c++) {
            y = fmaf(ALPHA_F, y, row[c]);
            row[c] = (y >= THETA_F) ? 1.0f : 0.0f;
        }
    }
    __syncthreads();

    // ---- coalesced store to g_l1[b][c][h0..h0+63] ----
    float* dstb = g_l1 + (size_t)b * CIN * HID + h0;
    for (int idx = tid; idx < CIN * 64; idx += 256) {
        int c = idx >> 6, hh = idx & 63;
        dstb[(size_t)c * HID + hh] = Ct[hh * 162 + c];
    }
}

// ===========================================================================
// Branch1 layer2: a2[b,o,t] = sum_h W2[o,h] * s1u8[b,h,t]  (unchanged)
// ===========================================================================
__global__ __launch_bounds__(256) void k_gemm_b1l2(const float* __restrict__ W2) {
    __shared__ ull   Wsd[2][32 * 21];
    __shared__ float Ssf[2][32 * 132];

    const int b  = blockIdx.y;
    const int t0 = blockIdx.x * 128;
    const int tid = threadIdx.x;
    const int tx = tid & 63, ty = tid >> 6;
    const unsigned char* Sb = g_s1u8 + (size_t)b * HID * TT + t0;

    ull acc[5];
#pragma unroll
    for (int q = 0; q < 5; q++) acc[q] = 0ULL;

    float vwf[3];  uchar4 vu[4];

#pragma unroll
    for (int it = 0; it < 3; it++) {
        int idx = tid + 256 * it;
        if (idx < 640) vwf[it] = W2[(idx >> 5) * HID + (idx & 31)];
    }
#pragma unroll
    for (int it = 0; it < 4; it++) {
        int idx = tid + 256 * it;
        vu[it] = *(const uchar4*)(Sb + (size_t)(idx >> 5) * TT + (idx & 31) * 4);
    }
    {
#pragma unroll
        for (int it = 0; it < 3; it++) {
            int idx = tid + 256 * it;
            if (idx < 640) Wsd[0][(idx & 31) * 21 + (idx >> 5)] = dup2(vwf[it]);
        }
#pragma unroll
        for (int it = 0; it < 4; it++) {
            int idx = tid + 256 * it;
            *(float4*)&Ssf[0][(idx >> 5) * 132 + (idx & 31) * 4] =
                make_float4((float)vu[it].x, (float)vu[it].y,
                            (float)vu[it].z, (float)vu[it].w);
        }
    }
    __syncthreads();

    for (int s = 0; s < HID / 32; s++) {
        const int buf = s & 1;
        const bool more = (s + 1 < HID / 32);
        if (more) {
            int k0 = (s + 1) * 32;
#pragma unroll
            for (int it = 0; it < 3; it++) {
                int idx = tid + 256 * it;
                if (idx < 640) vwf[it] = W2[(idx >> 5) * HID + k0 + (idx & 31)];
            }
#pragma unroll
            for (int it = 0; it < 4; it++) {
                int idx = tid + 256 * it;
                vu[it] = *(const uchar4*)(Sb + (size_t)(k0 + (idx >> 5)) * TT
                                             + (idx & 31) * 4);
            }
        }
#pragma unroll
        for (int k = 0; k < 32; k++) {
            const ull* Ar = &Wsd[buf][k * 21 + ty * 5];
            ull a0 = Ar[0], a1 = Ar[1], a2 = Ar[2], a3 = Ar[3], a4 = Ar[4];
            ull bv = *((const ull*)&Ssf[buf][k * 132] + tx);
            ffma2(acc[0], a0, bv);
            ffma2(acc[1], a1, bv);
            ffma2(acc[2], a2, bv);
            ffma2(acc[3], a3, bv);
            ffma2(acc[4], a4, bv);
        }
        if (more) {
#pragma unroll
            for (int it = 0; it < 3; it++) {
                int idx = tid + 256 * it;
                if (idx < 640) Wsd[buf^1][(idx & 31) * 21 + (idx >> 5)] = dup2(vwf[it]);
            }
#pragma unroll
            for (int it = 0; it < 4; it++) {
                int idx = tid + 256 * it;
                *(float4*)&Ssf[buf^1][(idx >> 5) * 132 + (idx & 31) * 4] =
                    make_float4((float)vu[it].x, (float)vu[it].y,
                                (float)vu[it].z, (float)vu[it].w);
            }
            __syncthreads();
        }
    }

#pragma unroll
    for (int q = 0; q < 5; q++) {
        int o = ty * 5 + q;
        *(ull*)(g_a2 + ((size_t)b * NOUT + o) * TT + t0 + tx * 2) = acc[q];
    }
}

// ---------------------------------------------------------------------------
// Warp-per-row output scans (unchanged)
// ---------------------------------------------------------------------------
__device__ __forceinline__ void scan_rows(const float* __restrict__ in,
                                          float* __restrict__ out,
                                          int len, int out_off) {
    __shared__ float4 buf[8][32];
    const int w = threadIdx.x >> 5, lane = threadIdx.x & 31;
    const int row = blockIdx.x * 8 + w;
    const float* ip = in + (size_t)row * len;
    float* op = out + (size_t)row * OUTT + out_off;
    const int nch = (len + 127) / 128;

    float y = 0.0f;
    int idx = lane * 4;
    float4 v = make_float4(0.f, 0.f, 0.f, 0.f);
    if (idx < len) v = *(const float4*)(ip + idx);

    for (int ch = 0; ch < nch; ch++) {
        buf[w][lane] = v;
        __syncwarp();
        int nidx = (ch + 1) * 128 + lane * 4;
        if (nidx < len) v = *(const float4*)(ip + nidx);
        if (lane == 0) {
            int n4 = (len - ch * 128) >> 2; if (n4 > 32) n4 = 32;
            for (int i = 0; i < n4; i++) {
                float4 u = buf[w][i]; float4 s;
                y = fmaf(ALPHA_F, y, u.x); s.x = (y >= THETA_F) ? 1.0f : 0.0f;
                y = fmaf(ALPHA_F, y, u.y); s.y = (y >= THETA_F) ? 1.0f : 0.0f;
                y = fmaf(ALPHA_F, y, u.z); s.z = (y >= THETA_F) ? 1.0f : 0.0f;
                y = fmaf(ALPHA_F, y, u.w); s.w = (y >= THETA_F) ? 1.0f : 0.0f;
                buf[w][i] = s;
            }
        }
        __syncwarp();
        int oi = ch * 128 + lane * 4;
        if (oi < len) *(float4*)(op + oi) = buf[w][lane];
        __syncwarp();
    }
}

__global__ __launch_bounds__(256) void k_scan_a2(float* __restrict__ out) {
    scan_rows(g_a2, out, TT, 0);
}
__global__ __launch_bounds__(256) void k_scan_l2(float* __restrict__ out) {
    scan_rows(g_l2, out, CIN, TT);
}

// ---------------------------------------------------------------------------
// Branch2 layer2: l2[b,o,c] = sum_h Wl2[o,h] * l1[b,c,h]  (unchanged)
// ---------------------------------------------------------------------------
__global__ __launch_bounds__(160) void k_gemm_b2l2(const float* __restrict__ Wl2) {
    __shared__ float Ws[4 * HID];
    const int og = blockIdx.x;
    const int b  = blockIdx.y;
    const int tid = threadIdx.x;

    for (int idx = tid; idx < 4 * HID; idx += 160)
        Ws[idx] = Wl2[(og * 4 + (idx >> 9)) * HID + (idx & (HID - 1))];
    __syncthreads();

    const int c = tid;
    if (c >= CIN) return;
    const float* Lb = g_l1 + ((size_t)b * CIN + c) * HID;
    float acc[4] = {0.f, 0.f, 0.f, 0.f};

#pragma unroll 4
    for (int h = 0; h < HID; h += 4) {
        float4 xv = *(const float4*)(Lb + h);
#pragma unroll
        for (int o = 0; o < 4; o++) {
            const float4 w = *(const float4*)&Ws[o * HID + h];
            acc[o] = fmaf(w.x, xv.x, acc[o]);
            acc[o] = fmaf(w.y, xv.y, acc[o]);
            acc[o] = fmaf(w.z, xv.z, acc[o]);
            acc[o] = fmaf(w.w, xv.w, acc[o]);
        }
    }
#pragma unroll
    for (int o = 0; o < 4; o++)
        g_l2[((size_t)b * NOUT + og * 4 + o) * CIN + c] = acc[o];
}

// ---------------------------------------------------------------------------
// Launch: fork branch-2 onto a secondary stream, join before return.
// ---------------------------------------------------------------------------
extern "C" void kernel_launch(void* const* d_in, const int* in_sizes, int n_in,
                              void* d_out, int out_size) {
    (void)in_sizes; (void)n_in; (void)out_size;
    const float* X    = (const float*)d_in[0];
    const float* W1   = (const float*)d_in[1];
    const float* W2   = (const float*)d_in[2];
    const float* Wl1  = (const float*)d_in[3];
    const float* Wl2  = (const float*)d_in[4];
    const int*   perm = (const int*)d_in[5];
    float* out = (float*)d_out;

    static cudaStream_t s2 = [] {
        cudaStream_t s; cudaStreamCreateWithFlags(&s, cudaStreamNonBlocking); return s;
    }();
    static cudaEvent_t evFork = [] {
        cudaEvent_t e; cudaEventCreateWithFlags(&e, cudaEventDisableTiming); return e;
    }();
    static cudaEvent_t evJoin = [] {
        cudaEvent_t e; cudaEventCreateWithFlags(&e, cudaEventDisableTiming); return e;
    }();

    cudaFuncSetAttribute(k_b1l1_psp, cudaFuncAttributeMaxDynamicSharedMemorySize, B1_SMEM);
    cudaFuncSetAttribute(k_b2l1_psp, cudaFuncAttributeMaxDynamicSharedMemorySize, B2_SMEM);

    // fork: branch 2 on s2
    cudaEventRecord(evFork, 0);
    cudaStreamWaitEvent(s2, evFork, 0);
    k_b2l1_psp<<<dim3(HID / 64, BB), 256, B2_SMEM, s2>>>(X, Wl1, perm);
    k_gemm_b2l2<<<dim3(5, BB), 160, 0, s2>>>(Wl2);
    k_scan_l2<<<BB * NOUT / 8, 256, 0, s2>>>(out);
    cudaEventRecord(evJoin, s2);

    // branch 1 on the main stream
    k_b1l1_psp<<<dim3(HID / 64, BB), 256, B1_SMEM>>>(X, W1);
    k_gemm_b1l2<<<dim3(TT / 128, BB), 256>>>(W2);
    k_scan_a2<<<BB * NOUT / 8, 256>>>(out);

    // join
    cudaStreamWaitEvent(0, evJoin, 0);
}

// round 14
// speedup vs baseline: 1.2306x; 1.1509x over previous
#include <cuda_runtime.h>
#include <cstdint>

// SLAYER constants
#define ALPHA_F 0.90483741803595952f
#define THETA_F 10.0f

// Problem dims
#define BB   32
#define CIN  156
#define TT   2048
#define HID  512
#define NOUT 20
#define OUTT (TT + CIN)   // 2204

typedef unsigned long long ull;

// ---------------------------------------------------------------------------
// Scratch
// ---------------------------------------------------------------------------
__device__ unsigned char g_s1u8[(size_t)BB * HID * TT];  // branch1 layer1 spikes (u8)
__device__ float         g_a2[(size_t)BB * NOUT * TT];   // branch1 layer2 pre-acts
__device__ float         g_l1[(size_t)BB * CIN * HID];   // branch2 spikes, [b][c][h]
__device__ float         g_l2[(size_t)BB * NOUT * CIN];  // branch2 layer2 pre-acts

// packed fp32x2 FMA: two independent rn-rounded fp32 FMAs (bitwise == scalar fmaf)
__device__ __forceinline__ void ffma2(ull& d, ull a, ull b) {
    asm("fma.rn.f32x2 %0, %1, %2, %0;" : "+l"(d) : "l"(a), "l"(b));
}
__device__ __forceinline__ ull dupf(float v) {            // (v, v) pack, ALU pipe
    ull r; asm("mov.b64 %0, {%1, %1};" : "=l"(r) : "f"(v)); return r;
}
__device__ __forceinline__ ull packf(float lo, float hi) {
    ull r; asm("mov.b64 %0, {%1, %2};" : "=l"(r) : "f"(lo), "f"(hi)); return r;
}

// ===========================================================================
// FUSED branch1 layer1 + psp + spike.
//   a1[b,h,t] = sum_c W1[h,c]*X[b,c,t] (c ascending 0..159, zero-padded)
// Block (h0 of 64, b) = grid (8,32), 128 threads, 16 t-tiles of 128.
// A PERSISTENT in smem as natural h-pairs (loaded once).
// B double-buffered; read vectorized float4, duplicated in registers (dupf).
// Thread: tx=tid&15 -> 8t, ty=tid>>4 (0..7) -> 8h (4 pairs).  acc[4][8].
// smem: Au ull[160][35] @0 (44800) | Bsf f32[2][16*132] @44800 (16896)
//       Ct f32[64][132] @61696 (33792) | Cu8 u8[64][132] @95488 (8448)
//       total 103936 -> 2 blocks/SM
// ===========================================================================
#define B1_SMEM 103936

__global__ __launch_bounds__(128) void k_b1l1_psp(const float* __restrict__ X,
                                                  const float* __restrict__ W1) {
    extern __shared__ char sm[];
    ull*   Au  = (ull*)sm;                         // [160][35] h-pairs
    float* Bsf = (float*)(sm + 44800);             // [2][16*132]
    float* Ct  = (float*)(sm + 61696);             // [64][132]
    unsigned char* Cu8 = (unsigned char*)(sm + 95488);

    const int b  = blockIdx.y;
    const int h0 = blockIdx.x * 64;
    const int tid = threadIdx.x;
    const int tx = tid & 15, ty = tid >> 4;        // ty 0..7
    const float* Xb = X + (size_t)b * CIN * TT;

    // ---- persistent A fill: Au[c][hp] = (W1[h0+2hp][c], W1[h0+2hp+1][c]) ----
    for (int hp = 0; hp < 32; hp++) {
        const float* r0 = W1 + (size_t)(h0 + 2 * hp) * CIN;
        const float* r1 = r0 + CIN;
        for (int c = tid; c < 160; c += 128) {
            float lo = (c < CIN) ? r0[c] : 0.0f;
            float hi = (c < CIN) ? r1[c] : 0.0f;
            Au[c * 35 + hp] = packf(lo, hi);
        }
    }

    float ycar = 0.0f;                             // psp carry (threads 0..63)

    for (int t0 = 0; t0 < TT; t0 += 128) {
        ull acc[4][8];
#pragma unroll
        for (int i = 0; i < 4; i++)
#pragma unroll
            for (int j = 0; j < 8; j++) acc[i][j] = 0ULL;

        // ---- prologue: slab 0 (16 k x 128 t) ----
        float4 vb[4];
#pragma unroll
        for (int it = 0; it < 4; it++) {
            int idx = tid + 128 * it;              // 0..511
            int kb = idx >> 5, t4 = idx & 31;
            vb[it] = (kb < CIN)
                   ? *(const float4*)(Xb + (size_t)kb * TT + t0 + t4 * 4)
                   : make_float4(0.f, 0.f, 0.f, 0.f);
        }
#pragma unroll
        for (int it = 0; it < 4; it++) {
            int idx = tid + 128 * it;
            int kb = idx >> 5, t4 = idx & 31;
            *(float4*)(Bsf + kb * 132 + t4 * 4) = vb[it];
        }
        __syncthreads();   // Bsf[0] (+ Au on first tile) visible

        for (int s = 0; s < 10; s++) {
            const int buf = s & 1;
            const bool more = (s + 1 < 10);
            if (more) {
                int k0 = (s + 1) * 16;
#pragma unroll
                for (int it = 0; it < 4; it++) {
                    int idx = tid + 128 * it;
                    int kb = idx >> 5, t4 = idx & 31;
                    int ck = k0 + kb;
                    vb[it] = (ck < CIN)
                           ? *(const float4*)(Xb + (size_t)ck * TT + t0 + t4 * 4)
                           : make_float4(0.f, 0.f, 0.f, 0.f);
                }
            }
            const float* Bb = Bsf + buf * (16 * 132);
#pragma unroll
            for (int k = 0; k < 16; k++) {
                const ull* Ar = Au + (s * 16 + k) * 35 + ty * 4;
                ull a0 = Ar[0], a1 = Ar[1], a2 = Ar[2], a3 = Ar[3];
                float4 v0 = *(const float4*)(Bb + k * 132 + tx * 8);
                float4 v1 = *(const float4*)(Bb + k * 132 + tx * 8 + 4);
                ull bd0 = dupf(v0.x), bd1 = dupf(v0.y),
                    bd2 = dupf(v0.z), bd3 = dupf(v0.w),
                    bd4 = dupf(v1.x), bd5 = dupf(v1.y),
                    bd6 = dupf(v1.z), bd7 = dupf(v1.w);
                ffma2(acc[0][0], a0, bd0); ffma2(acc[1][0], a1, bd0);
                ffma2(acc[2][0], a2, bd0); ffma2(acc[3][0], a3, bd0);
                ffma2(acc[0][1], a0, bd1); ffma2(acc[1][1], a1, bd1);
                ffma2(acc[2][1], a2, bd1); ffma2(acc[3][1], a3, bd1);
                ffma2(acc[0][2], a0, bd2); ffma2(acc[1][2], a1, bd2);
                ffma2(acc[2][2], a2, bd2); ffma2(acc[3][2], a3, bd2);
                ffma2(acc[0][3], a0, bd3); ffma2(acc[1][3], a1, bd3);
                ffma2(acc[2][3], a2, bd3); ffma2(acc[3][3], a3, bd3);
                ffma2(acc[0][4], a0, bd4); ffma2(acc[1][4], a1, bd4);
                ffma2(acc[2][4], a2, bd4); ffma2(acc[3][4], a3, bd4);
                ffma2(acc[0][5], a0, bd5); ffma2(acc[1][5], a1, bd5);
                ffma2(acc[2][5], a2, bd5); ffma2(acc[3][5], a3, bd5);
                ffma2(acc[0][6], a0, bd6); ffma2(acc[1][6], a1, bd6);
                ffma2(acc[2][6], a2, bd6); ffma2(acc[3][6], a3, bd6);
                ffma2(acc[0][7], a0, bd7); ffma2(acc[1][7], a1, bd7);
                ffma2(acc[2][7], a2, bd7); ffma2(acc[3][7], a3, bd7);
            }
            if (more) {
                float* Bd = Bsf + (buf ^ 1) * (16 * 132);
#pragma unroll
                for (int it = 0; it < 4; it++) {
                    int idx = tid + 128 * it;
                    int kb = idx >> 5, t4 = idx & 31;
                    *(float4*)(Bd + kb * 132 + t4 * 4) = vb[it];
                }
                __syncthreads();
            }
        }

        // ---- epilogue: acc (pairs over h) -> Ct[h][t] ----
#pragma unroll
        for (int i = 0; i < 4; i++)
#pragma unroll
            for (int j = 0; j < 8; j++) {
                float2 f = *(float2*)&acc[i][j];
                int t = tx * 8 + j;
                Ct[(ty * 8 + 2 * i) * 132 + t]     = f.x;
                Ct[(ty * 8 + 2 * i + 1) * 132 + t] = f.y;
            }
        __syncthreads();

        // ---- fused psp scan + spike (threads 0..63) ----
        if (tid < 64) {
            float y = ycar;
            const float* row = Ct + tid * 132;
            unsigned* orow = (unsigned*)(Cu8 + tid * 132);
#pragma unroll 4
            for (int q = 0; q < 32; q++) {
                float4 v = *(const float4*)(row + q * 4);
                unsigned pk;
                y = fmaf(ALPHA_F, y, v.x); pk  = (y >= THETA_F) ? 1u : 0u;
                y = fmaf(ALPHA_F, y, v.y); pk |= (y >= THETA_F) ? (1u<<8) : 0u;
                y = fmaf(ALPHA_F, y, v.z); pk |= (y >= THETA_F) ? (1u<<16) : 0u;
                y = fmaf(ALPHA_F, y, v.w); pk |= (y >= THETA_F) ? (1u<<24) : 0u;
                orow[q] = pk;
            }
            ycar = y;
        }
        __syncthreads();

        // ---- coalesced u8 copy-out ----
        unsigned char* dstb = g_s1u8 + ((size_t)b * HID + h0) * TT + t0;
#pragma unroll
        for (int it = 0; it < 16; it++) {
            int idx = tid + 128 * it;              // 0..2047
            int row = idx >> 5, q = idx & 31;
            unsigned v = *(const unsigned*)(Cu8 + row * 132 + q * 4);
            *(unsigned*)(dstb + (size_t)row * TT + q * 4) = v;
        }
        __syncthreads();   // protects Bsf/Ct/Cu8 for next tile
    }
}

// ===========================================================================
// FUSED branch2 layer1 + psp + spike.
//   l1a[b,h,c] = sum_t Wl1[h,t]*X[b,perm[c],t] (t ascending 0..2047)
// Block (h0 of 64, b) = grid (8,32), 128 threads, 128 slabs of 16 k.
// A plain floats in smem, read vectorized + reg-dup; B natural c-pairs.
// Thread: tx=tid&15 -> c-pairs {tx+16q} q=0..4; ty=tid>>4 (0..7) -> 8h.
// smem: Af f32[2][16*68] @0 (8704) | Bsd ull[2][16*81] @8704 (20736)
//       Ct f32[64][162] @29440 (41472) | prow @70912 (640)  total 71552
// ===========================================================================
#define B2_SMEM 71552

__global__ __launch_bounds__(128) void k_b2l1_psp(const float* __restrict__ X,
                                                  const float* __restrict__ Wl1,
                                                  const int* __restrict__ perm) {
    extern __shared__ char sm[];
    float* Af  = (float*)sm;                      // [2][16*68]
    ull*   Bsd = (ull*)(sm + 8704);               // [2][16*81]
    float* Ct  = (float*)(sm + 29440);            // [64][162]
    int*   prow = (int*)(sm + 70912);

    const int b  = blockIdx.y;
    const int h0 = blockIdx.x * 64;
    const int tid = threadIdx.x;
    const int tx = tid & 15, ty = tid >> 4;       // ty 0..7
    const int ha = tid >> 1, kqa = tid & 1;       // A fill: h=ha, k=kqa*8..+7
    const float* Xb = X + (size_t)b * CIN * TT;
    const float* Wr = Wl1 + (size_t)(h0 + ha) * TT + kqa * 8;

    // FIX: 128 threads must fill all 160 prow entries (round-13 bug: tid<160
    // guard left prow[128..159] uninitialized -> illegal gmem access).
    for (int i = tid; i < 160; i += 128)
        prow[i] = (i < CIN) ? perm[i] : 0;
    __syncthreads();

    ull acc[8][5];
#pragma unroll
    for (int i = 0; i < 8; i++)
#pragma unroll
        for (int q = 0; q < 5; q++) acc[i][q] = 0ULL;

    // ---- prologue: slab 0 ----
    float4 va0, va1, vbx[5];
    va0 = *(const float4*)(Wr);
    va1 = *(const float4*)(Wr + 4);
#pragma unroll
    for (int it = 0; it < 5; it++) {
        int idx = tid + 128 * it;                 // 0..639
        int c = idx >> 2, kq = idx & 3;
        vbx[it] = *(const float4*)(Xb + (size_t)prow[c] * TT + kq * 4);
    }
    {
        float* Ad = Af;
        int kb = kqa * 8;
        Ad[(kb+0)*68 + ha] = va0.x;  Ad[(kb+1)*68 + ha] = va0.y;
        Ad[(kb+2)*68 + ha] = va0.z;  Ad[(kb+3)*68 + ha] = va0.w;
        Ad[(kb+4)*68 + ha] = va1.x;  Ad[(kb+5)*68 + ha] = va1.y;
        Ad[(kb+6)*68 + ha] = va1.z;  Ad[(kb+7)*68 + ha] = va1.w;
        ull* Bd = Bsd;
#pragma unroll
        for (int it = 0; it < 5; it++) {
            int idx = tid + 128 * it;
            int c = idx >> 2, kq = idx & 3;
            int p = c >> 1, hf = c & 1;
            ((float*)(Bd + (size_t)(kq*4+0)*81 + p))[hf] = vbx[it].x;
            ((float*)(Bd + (size_t)(kq*4+1)*81 + p))[hf] = vbx[it].y;
            ((float*)(Bd + (size_t)(kq*4+2)*81 + p))[hf] = vbx[it].z;
            ((float*)(Bd + (size_t)(kq*4+3)*81 + p))[hf] = vbx[it].w;
        }
    }
    __syncthreads();

    for (int s = 0; s < TT / 16; s++) {
        const int buf = s & 1;
        const bool more = (s + 1 < TT / 16);
        if (more) {
            int k0 = (s + 1) * 16;
            va0 = *(const float4*)(Wr + k0);
            va1 = *(const float4*)(Wr + k0 + 4);
#pragma unroll
            for (int it = 0; it < 5; it++) {
                int idx = tid + 128 * it;
                int c = idx >> 2, kq = idx & 3;
                vbx[it] = *(const float4*)(Xb + (size_t)prow[c] * TT + k0 + kq * 4);
            }
        }
        const float* Ab = Af + buf * (16 * 68);
        const ull*   Bb = Bsd + buf * (16 * 81);
#pragma unroll
        for (int k = 0; k < 16; k++) {
            float4 w0 = *(const float4*)(Ab + k * 68 + ty * 8);
            float4 w1 = *(const float4*)(Ab + k * 68 + ty * 8 + 4);
            ull ad0 = dupf(w0.x), ad1 = dupf(w0.y),
                ad2 = dupf(w0.z), ad3 = dupf(w0.w),
                ad4 = dupf(w1.x), ad5 = dupf(w1.y),
                ad6 = dupf(w1.z), ad7 = dupf(w1.w);
            const ull* Br = Bb + k * 81;
            ull b0 = Br[tx], b1 = Br[tx+16], b2 = Br[tx+32],
                b3 = Br[tx+48], b4 = Br[tx+64];
            ffma2(acc[0][0], ad0, b0); ffma2(acc[1][0], ad1, b0);
            ffma2(acc[2][0], ad2, b0); ffma2(acc[3][0], ad3, b0);
            ffma2(acc[4][0], ad4, b0); ffma2(acc[5][0], ad5, b0);
            ffma2(acc[6][0], ad6, b0); ffma2(acc[7][0], ad7, b0);
            ffma2(acc[0][1], ad0, b1); ffma2(acc[1][1], ad1, b1);
            ffma2(acc[2][1], ad2, b1); ffma2(acc[3][1], ad3, b1);
            ffma2(acc[4][1], ad4, b1); ffma2(acc[5][1], ad5, b1);
            ffma2(acc[6][1], ad6, b1); ffma2(acc[7][1], ad7, b1);
            ffma2(acc[0][2], ad0, b2); ffma2(acc[1][2], ad1, b2);
            ffma2(acc[2][2], ad2, b2); ffma2(acc[3][2], ad3, b2);
            ffma2(acc[4][2], ad4, b2); ffma2(acc[5][2], ad5, b2);
            ffma2(acc[6][2], ad6, b2); ffma2(acc[7][2], ad7, b2);
            ffma2(acc[0][3], ad0, b3); ffma2(acc[1][3], ad1, b3);
            ffma2(acc[2][3], ad2, b3); ffma2(acc[3][3], ad3, b3);
            ffma2(acc[4][3], ad4, b3); ffma2(acc[5][3], ad5, b3);
            ffma2(acc[6][3], ad6, b3); ffma2(acc[7][3], ad7, b3);
            ffma2(acc[0][4], ad0, b4); ffma2(acc[1][4], ad1, b4);
            ffma2(acc[2][4], ad2, b4); ffma2(acc[3][4], ad3, b4);
            ffma2(acc[4][4], ad4, b4); ffma2(acc[5][4], ad5, b4);
            ffma2(acc[6][4], ad6, b4); ffma2(acc[7][4], ad7, b4);
        }
        if (more) {
            float* Ad = Af + (buf ^ 1) * (16 * 68);
            ull*   Bd = Bsd + (buf ^ 1) * (16 * 81);
            int kb = kqa * 8;
            Ad[(kb+0)*68 + ha] = va0.x;  Ad[(kb+1)*68 + ha] = va0.y;
            Ad[(kb+2)*68 + ha] = va0.z;  Ad[(kb+3)*68 + ha] = va0.w;
            Ad[(kb+4)*68 + ha] = va1.x;  Ad[(kb+5)*68 + ha] = va1.y;
            Ad[(kb+6)*68 + ha] = va1.z;  Ad[(kb+7)*68 + ha] = va1.w;
#pragma unroll
            for (int it = 0; it < 5; it++) {
                int idx = tid + 128 * it;
                int c = idx >> 2, kq = idx & 3;
                int p = c >> 1, hf = c & 1;
                ((float*)(Bd + (size_t)(kq*4+0)*81 + p))[hf] = vbx[it].x;
                ((float*)(Bd + (size_t)(kq*4+1)*81 + p))[hf] = vbx[it].y;
                ((float*)(Bd + (size_t)(kq*4+2)*81 + p))[hf] = vbx[it].z;
                ((float*)(Bd + (size_t)(kq*4+3)*81 + p))[hf] = vbx[it].w;
            }
            __syncthreads();
        }
    }

    // ---- epilogue: acc (pairs over c at p = tx+16q) -> Ct[h][c] ----
    __syncthreads();
#pragma unroll
    for (int i = 0; i < 8; i++)
#pragma unroll
        for (int q = 0; q < 5; q++) {
            float2 f = *(float2*)&acc[i][q];
            int p = tx + 16 * q;
            *(float2*)(Ct + (ty * 8 + i) * 162 + 2 * p) = f;
        }
    __syncthreads();

    // ---- fused psp scan over c + spike (threads 0..63, in-place) ----
    if (tid < 64) {
        float y = 0.0f;
        float* row = Ct + tid * 162;
#pragma unroll 4
        for (int c = 0; c < CIN; c++) {
            y = fmaf(ALPHA_F, y, row[c]);
            row[c] = (y >= THETA_F) ? 1.0f : 0.0f;
        }
    }
    __syncthreads();

    // ---- coalesced store to g_l1[b][c][h0..h0+63] ----
    float* dstb = g_l1 + (size_t)b * CIN * HID + h0;
#pragma unroll 4
    for (int idx = tid; idx < CIN * 64; idx += 128) {
        int c = idx >> 6, hh = idx & 63;
        dstb[(size_t)c * HID + hh] = Ct[hh * 162 + c];
    }
}

// ===========================================================================
// Branch1 layer2: a2[b,o,t] = sum_h W2[o,h] * s1u8[b,h,t]  (unchanged)
// ===========================================================================
__global__ __launch_bounds__(256) void k_gemm_b1l2(const float* __restrict__ W2) {
    __shared__ ull   Wsd[2][32 * 21];
    __shared__ float Ssf[2][32 * 132];

    const int b  = blockIdx.y;
    const int t0 = blockIdx.x * 128;
    const int tid = threadIdx.x;
    const int tx = tid & 63, ty = tid >> 6;
    const unsigned char* Sb = g_s1u8 + (size_t)b * HID * TT + t0;

    ull acc[5];
#pragma unroll
    for (int q = 0; q < 5; q++) acc[q] = 0ULL;

    float vwf[3];  uchar4 vu[4];

#pragma unroll
    for (int it = 0; it < 3; it++) {
        int idx = tid + 256 * it;
        if (idx < 640) vwf[it] = W2[(idx >> 5) * HID + (idx & 31)];
    }
#pragma unroll
    for (int it = 0; it < 4; it++) {
        int idx = tid + 256 * it;
        vu[it] = *(const uchar4*)(Sb + (size_t)(idx >> 5) * TT + (idx & 31) * 4);
    }
    {
#pragma unroll
        for (int it = 0; it < 3; it++) {
            int idx = tid + 256 * it;
            if (idx < 640) Wsd[0][(idx & 31) * 21 + (idx >> 5)] = dupf(vwf[it]);
        }
#pragma unroll
        for (int it = 0; it < 4; it++) {
            int idx = tid + 256 * it;
            *(float4*)&Ssf[0][(idx >> 5) * 132 + (idx & 31) * 4] =
                make_float4((float)vu[it].x, (float)vu[it].y,
                            (float)vu[it].z, (float)vu[it].w);
        }
    }
    __syncthreads();

    for (int s = 0; s < HID / 32; s++) {
        const int buf = s & 1;
        const bool more = (s + 1 < HID / 32);
        if (more) {
            int k0 = (s + 1) * 32;
#pragma unroll
            for (int it = 0; it < 3; it++) {
                int idx = tid + 256 * it;
                if (idx < 640) vwf[it] = W2[(idx >> 5) * HID + k0 + (idx & 31)];
            }
#pragma unroll
            for (int it = 0; it < 4; it++) {
                int idx = tid + 256 * it;
                vu[it] = *(const uchar4*)(Sb + (size_t)(k0 + (idx >> 5)) * TT
                                             + (idx & 31) * 4);
            }
        }
#pragma unroll
        for (int k = 0; k < 32; k++) {
            const ull* Ar = &Wsd[buf][k * 21 + ty * 5];
            ull a0 = Ar[0], a1 = Ar[1], a2 = Ar[2], a3 = Ar[3], a4 = Ar[4];
            ull bv = *((const ull*)&Ssf[buf][k * 132] + tx);
            ffma2(acc[0], a0, bv);
            ffma2(acc[1], a1, bv);
            ffma2(acc[2], a2, bv);
            ffma2(acc[3], a3, bv);
            ffma2(acc[4], a4, bv);
        }
        if (more) {
#pragma unroll
            for (int it = 0; it < 3; it++) {
                int idx = tid + 256 * it;
                if (idx < 640) Wsd[buf^1][(idx & 31) * 21 + (idx >> 5)] = dupf(vwf[it]);
            }
#pragma unroll
            for (int it = 0; it < 4; it++) {
                int idx = tid + 256 * it;
                *(float4*)&Ssf[buf^1][(idx >> 5) * 132 + (idx & 31) * 4] =
                    make_float4((float)vu[it].x, (float)vu[it].y,
                                (float)vu[it].z, (float)vu[it].w);
            }
            __syncthreads();
        }
    }

#pragma unroll
    for (int q = 0; q < 5; q++) {
        int o = ty * 5 + q;
        *(ull*)(g_a2 + ((size_t)b * NOUT + o) * TT + t0 + tx * 2) = acc[q];
    }
}

// ---------------------------------------------------------------------------
// Warp-per-row output scans (unchanged)
// ---------------------------------------------------------------------------
__device__ __forceinline__ void scan_rows(const float* __restrict__ in,
                                          float* __restrict__ out,
                                          int len, int out_off) {
    __shared__ float4 buf[8][32];
    const int w = threadIdx.x >> 5, lane = threadIdx.x & 31;
    const int row = blockIdx.x * 8 + w;
    const float* ip = in + (size_t)row * len;
    float* op = out + (size_t)row * OUTT + out_off;
    const int nch = (len + 127) / 128;

    float y = 0.0f;
    int idx = lane * 4;
    float4 v = make_float4(0.f, 0.f, 0.f, 0.f);
    if (idx < len) v = *(const float4*)(ip + idx);

    for (int ch = 0; ch < nch; ch++) {
        buf[w][lane] = v;
        __syncwarp();
        int nidx = (ch + 1) * 128 + lane * 4;
        if (nidx < len) v = *(const float4*)(ip + nidx);
        if (lane == 0) {
            int n4 = (len - ch * 128) >> 2; if (n4 > 32) n4 = 32;
            for (int i = 0; i < n4; i++) {
                float4 u = buf[w][i]; float4 s;
                y = fmaf(ALPHA_F, y, u.x); s.x = (y >= THETA_F) ? 1.0f : 0.0f;
                y = fmaf(ALPHA_F, y, u.y); s.y = (y >= THETA_F) ? 1.0f : 0.0f;
                y = fmaf(ALPHA_F, y, u.z); s.z = (y >= THETA_F) ? 1.0f : 0.0f;
                y = fmaf(ALPHA_F, y, u.w); s.w = (y >= THETA_F) ? 1.0f : 0.0f;
                buf[w][i] = s;
            }
        }
        __syncwarp();
        int oi = ch * 128 + lane * 4;
        if (oi < len) *(float4*)(op + oi) = buf[w][lane];
        __syncwarp();
    }
}

__global__ __launch_bounds__(256) void k_scan_a2(float* __restrict__ out) {
    scan_rows(g_a2, out, TT, 0);
}
__global__ __launch_bounds__(256) void k_scan_l2(float* __restrict__ out) {
    scan_rows(g_l2, out, CIN, TT);
}

// ---------------------------------------------------------------------------
// Branch2 layer2: l2[b,o,c] = sum_h Wl2[o,h] * l1[b,c,h]  (unchanged)
// ---------------------------------------------------------------------------
__global__ __launch_bounds__(160) void k_gemm_b2l2(const float* __restrict__ Wl2) {
    __shared__ float Ws[4 * HID];
    const int og = blockIdx.x;
    const int b  = blockIdx.y;
    const int tid = threadIdx.x;

    for (int idx = tid; idx < 4 * HID; idx += 160)
        Ws[idx] = Wl2[(og * 4 + (idx >> 9)) * HID + (idx & (HID - 1))];
    __syncthreads();

    const int c = tid;
    if (c >= CIN) return;
    const float* Lb = g_l1 + ((size_t)b * CIN + c) * HID;
    float acc[4] = {0.f, 0.f, 0.f, 0.f};

#pragma unroll 4
    for (int h = 0; h < HID; h += 4) {
        float4 xv = *(const float4*)(Lb + h);
#pragma unroll
        for (int o = 0; o < 4; o++) {
            const float4 w = *(const float4*)&Ws[o * HID + h];
            acc[o] = fmaf(w.x, xv.x, acc[o]);
            acc[o] = fmaf(w.y, xv.y, acc[o]);
            acc[o] = fmaf(w.z, xv.z, acc[o]);
            acc[o] = fmaf(w.w, xv.w, acc[o]);
        }
    }
#pragma unroll
    for (int o = 0; o < 4; o++)
        g_l2[((size_t)b * NOUT + og * 4 + o) * CIN + c] = acc[o];
}

// ---------------------------------------------------------------------------
// Launch: fork branch-2 onto a secondary stream, join before return.
// ---------------------------------------------------------------------------
extern "C" void kernel_launch(void* const* d_in, const int* in_sizes, int n_in,
                              void* d_out, int out_size) {
    (void)in_sizes; (void)n_in; (void)out_size;
    const float* X    = (const float*)d_in[0];
    const float* W1   = (const float*)d_in[1];
    const float* W2   = (const float*)d_in[2];
    const float* Wl1  = (const float*)d_in[3];
    const float* Wl2  = (const float*)d_in[4];
    const int*   perm = (const int*)d_in[5];
    float* out = (float*)d_out;

    static cudaStream_t s2 = [] {
        cudaStream_t s; cudaStreamCreateWithFlags(&s, cudaStreamNonBlocking); return s;
    }();
    static cudaEvent_t evFork = [] {
        cudaEvent_t e; cudaEventCreateWithFlags(&e, cudaEventDisableTiming); return e;
    }();
    static cudaEvent_t evJoin = [] {
        cudaEvent_t e; cudaEventCreateWithFlags(&e, cudaEventDisableTiming); return e;
    }();

    cudaFuncSetAttribute(k_b1l1_psp, cudaFuncAttributeMaxDynamicSharedMemorySize, B1_SMEM);
    cudaFuncSetAttribute(k_b2l1_psp, cudaFuncAttributeMaxDynamicSharedMemorySize, B2_SMEM);

    // fork: branch 2 on s2
    cudaEventRecord(evFork, 0);
    cudaStreamWaitEvent(s2, evFork, 0);
    k_b2l1_psp<<<dim3(HID / 64, BB), 128, B2_SMEM, s2>>>(X, Wl1, perm);
    k_gemm_b2l2<<<dim3(5, BB), 160, 0, s2>>>(Wl2);
    k_scan_l2<<<BB * NOUT / 8, 256, 0, s2>>>(out);
    cudaEventRecord(evJoin, s2);

    // branch 1 on the main stream
    k_b1l1_psp<<<dim3(HID / 64, BB), 128, B1_SMEM>>>(X, W1);
    k_gemm_b1l2<<<dim3(TT / 128, BB), 256>>>(W2);
    k_scan_a2<<<BB * NOUT / 8, 256>>>(out);

    // join
    cudaStreamWaitEvent(0, evJoin, 0);
}

// round 16
// speedup vs baseline: 1.2415x; 1.0089x over previous
#include <cuda_runtime.h>
#include <cstdint>

// SLAYER constants
#define ALPHA_F 0.90483741803595952f
#define THETA_F 10.0f

// Problem dims
#define BB   32
#define CIN  156
#define TT   2048
#define HID  512
#define NOUT 20
#define OUTT (TT + CIN)   // 2204

typedef unsigned long long ull;

// ---------------------------------------------------------------------------
// Scratch
// ---------------------------------------------------------------------------
__device__ unsigned char g_s1u8[(size_t)BB * HID * TT];  // branch1 layer1 spikes (u8)
__device__ float         g_a2[(size_t)BB * NOUT * TT];   // branch1 layer2 pre-acts
__device__ float         g_l1[(size_t)BB * CIN * HID];   // branch2 spikes, [b][c][h]
__device__ float         g_l2[(size_t)BB * NOUT * CIN];  // branch2 layer2 pre-acts

// packed fp32x2 FMA: two independent rn-rounded fp32 FMAs (bitwise == scalar fmaf)
__device__ __forceinline__ void ffma2(ull& d, ull a, ull b) {
    asm("fma.rn.f32x2 %0, %1, %2, %0;" : "+l"(d) : "l"(a), "l"(b));
}
__device__ __forceinline__ ull dupf(float v) {            // (v, v) pack, ALU pipe
    ull r; asm("mov.b64 %0, {%1, %1};" : "=l"(r) : "f"(v)); return r;
}
__device__ __forceinline__ ull packf(float lo, float hi) {
    ull r; asm("mov.b64 %0, {%1, %2};" : "=l"(r) : "f"(lo), "f"(hi)); return r;
}

// ===========================================================================
// FUSED branch1 layer1 + psp + spike.  256 threads, microtile 8h x 4t.
//   a1[b,h,t] = sum_c W1[h,c]*X[b,c,t] (c ascending 0..159, zero-padded)
// Block (h0 of 64, b) = grid (8,32), 16 t-tiles of 128.
// A PERSISTENT in smem as natural h-pairs (loaded once), stride 36 (16B-align).
// B double-buffered; read float4, duplicated in registers (dupf).
// Thread: tx=tid&31 -> 4t, ty=tid>>5 (0..7) -> 8h (4 pairs).  acc[4][4].
// smem: Au ull[160][36] @0 (46080) | Bsf f32[2][16*132] @46080 (16896)
//       Ct f32[64][132] @62976 (33792) | Cu8 u8[64][132] @96768 (8448)
//       total 105216 -> 2 blocks/SM, 16 warps/SM
// ===========================================================================
#define B1_SMEM 105216

__global__ __launch_bounds__(256) void k_b1l1_psp(const float* __restrict__ X,
                                                  const float* __restrict__ W1) {
    extern __shared__ char sm[];
    ull*   Au  = (ull*)sm;                         // [160][36] h-pairs
    float* Bsf = (float*)(sm + 46080);             // [2][16*132]
    float* Ct  = (float*)(sm + 62976);             // [64][132]
    unsigned char* Cu8 = (unsigned char*)(sm + 96768);

    const int b  = blockIdx.y;
    const int h0 = blockIdx.x * 64;
    const int tid = threadIdx.x;
    const int tx = tid & 31, ty = tid >> 5;        // ty 0..7
    const float* Xb = X + (size_t)b * CIN * TT;

    // ---- persistent A fill: Au[c][hp] = (W1[h0+2hp][c], W1[h0+2hp+1][c]) ----
    for (int hp = 0; hp < 32; hp++) {
        const float* r0 = W1 + (size_t)(h0 + 2 * hp) * CIN;
        const float* r1 = r0 + CIN;
        for (int c = tid; c < 160; c += 256) {
            float lo = (c < CIN) ? r0[c] : 0.0f;
            float hi = (c < CIN) ? r1[c] : 0.0f;
            Au[c * 36 + hp] = packf(lo, hi);
        }
    }

    float ycar = 0.0f;                             // psp carry (threads 0..63)

    for (int t0 = 0; t0 < TT; t0 += 128) {
        ull acc[4][4];
#pragma unroll
        for (int i = 0; i < 4; i++)
#pragma unroll
            for (int j = 0; j < 4; j++) acc[i][j] = 0ULL;

        // ---- prologue: slab 0 (16 k x 128 t) ----
        float4 vb[2];
#pragma unroll
        for (int it = 0; it < 2; it++) {
            int idx = tid + 256 * it;              // 0..511
            int kb = idx >> 5, t4 = idx & 31;
            vb[it] = (kb < CIN)
                   ? *(const float4*)(Xb + (size_t)kb * TT + t0 + t4 * 4)
                   : make_float4(0.f, 0.f, 0.f, 0.f);
        }
#pragma unroll
        for (int it = 0; it < 2; it++) {
            int idx = tid + 256 * it;
            int kb = idx >> 5, t4 = idx & 31;
            *(float4*)(Bsf + kb * 132 + t4 * 4) = vb[it];
        }
        __syncthreads();   // Bsf[0] (+ Au on first tile) visible

        for (int s = 0; s < 10; s++) {
            const int buf = s & 1;
            const bool more = (s + 1 < 10);
            if (more) {
                int k0 = (s + 1) * 16;
#pragma unroll
                for (int it = 0; it < 2; it++) {
                    int idx = tid + 256 * it;
                    int kb = idx >> 5, t4 = idx & 31;
                    int ck = k0 + kb;
                    vb[it] = (ck < CIN)
                           ? *(const float4*)(Xb + (size_t)ck * TT + t0 + t4 * 4)
                           : make_float4(0.f, 0.f, 0.f, 0.f);
                }
            }
            const float* Bb = Bsf + buf * (16 * 132);
#pragma unroll
            for (int k = 0; k < 16; k++) {
                const ull* Ar = Au + (s * 16 + k) * 36 + ty * 4;
                ull a0 = Ar[0], a1 = Ar[1], a2 = Ar[2], a3 = Ar[3];
                float4 v0 = *(const float4*)(Bb + k * 132 + tx * 4);
                ull bd0 = dupf(v0.x), bd1 = dupf(v0.y),
                    bd2 = dupf(v0.z), bd3 = dupf(v0.w);
                ffma2(acc[0][0], a0, bd0); ffma2(acc[1][0], a1, bd0);
                ffma2(acc[2][0], a2, bd0); ffma2(acc[3][0], a3, bd0);
                ffma2(acc[0][1], a0, bd1); ffma2(acc[1][1], a1, bd1);
                ffma2(acc[2][1], a2, bd1); ffma2(acc[3][1], a3, bd1);
                ffma2(acc[0][2], a0, bd2); ffma2(acc[1][2], a1, bd2);
                ffma2(acc[2][2], a2, bd2); ffma2(acc[3][2], a3, bd2);
                ffma2(acc[0][3], a0, bd3); ffma2(acc[1][3], a1, bd3);
                ffma2(acc[2][3], a2, bd3); ffma2(acc[3][3], a3, bd3);
            }
            if (more) {
                float* Bd = Bsf + (buf ^ 1) * (16 * 132);
#pragma unroll
                for (int it = 0; it < 2; it++) {
                    int idx = tid + 256 * it;
                    int kb = idx >> 5, t4 = idx & 31;
                    *(float4*)(Bd + kb * 132 + t4 * 4) = vb[it];
                }
                __syncthreads();
            }
        }

        // ---- epilogue: acc (pairs over h) -> Ct[h][t] ----
#pragma unroll
        for (int i = 0; i < 4; i++)
#pragma unroll
            for (int j = 0; j < 4; j++) {
                float2 f = *(float2*)&acc[i][j];
                int t = tx * 4 + j;
                Ct[(ty * 8 + 2 * i) * 132 + t]     = f.x;
                Ct[(ty * 8 + 2 * i + 1) * 132 + t] = f.y;
            }
        __syncthreads();

        // ---- fused psp scan + spike (threads 0..63) ----
        if (tid < 64) {
            float y = ycar;
            const float* row = Ct + tid * 132;
            unsigned* orow = (unsigned*)(Cu8 + tid * 132);
#pragma unroll 4
            for (int q = 0; q < 32; q++) {
                float4 v = *(const float4*)(row + q * 4);
                unsigned pk;
                y = fmaf(ALPHA_F, y, v.x); pk  = (y >= THETA_F) ? 1u : 0u;
                y = fmaf(ALPHA_F, y, v.y); pk |= (y >= THETA_F) ? (1u<<8) : 0u;
                y = fmaf(ALPHA_F, y, v.z); pk |= (y >= THETA_F) ? (1u<<16) : 0u;
                y = fmaf(ALPHA_F, y, v.w); pk |= (y >= THETA_F) ? (1u<<24) : 0u;
                orow[q] = pk;
            }
            ycar = y;
        }
        __syncthreads();

        // ---- coalesced u8 copy-out ----
        unsigned char* dstb = g_s1u8 + ((size_t)b * HID + h0) * TT + t0;
#pragma unroll
        for (int it = 0; it < 8; it++) {
            int idx = tid + 256 * it;              // 0..2047
            int row = idx >> 5, q = idx & 31;
            unsigned v = *(const unsigned*)(Cu8 + row * 132 + q * 4);
            *(unsigned*)(dstb + (size_t)row * TT + q * 4) = v;
        }
        __syncthreads();   // protects Bsf/Ct/Cu8 for next tile
    }
}

// ===========================================================================
// FUSED branch2 layer1 + psp + spike.  256 threads, microtile 4h x 10c.
//   l1a[b,h,c] = sum_t Wl1[h,t]*X[b,perm[c],t] (t ascending 0..2047)
// Block (h0 of 64, b) = grid (8,32), 128 slabs of 16 k.
// A plain floats in smem, read one aligned float4 + reg-dup; B natural c-pairs
// strided (conflict-free LDS.64).
// Thread: tx=tid&15 -> c-pairs {tx+16q} q=0..4; ty=tid>>4 (0..15) -> 4h.
// smem: Af f32[2][16*68] @0 (8704) | Bsd ull[2][16*81] @8704 (20736)
//       Ct f32[64][162] @29440 (41472) | prow @70912 (640)  total 71552
// ===========================================================================
#define B2_SMEM 71552

__global__ __launch_bounds__(256) void k_b2l1_psp(const float* __restrict__ X,
                                                  const float* __restrict__ Wl1,
                                                  const int* __restrict__ perm) {
    extern __shared__ char sm[];
    float* Af  = (float*)sm;                      // [2][16*68]
    ull*   Bsd = (ull*)(sm + 8704);               // [2][16*81]
    float* Ct  = (float*)(sm + 29440);            // [64][162]
    int*   prow = (int*)(sm + 70912);

    const int b  = blockIdx.y;
    const int h0 = blockIdx.x * 64;
    const int tid = threadIdx.x;
    const int tx = tid & 15, ty = tid >> 4;       // ty 0..15
    const int ha = tid >> 2, kqa = tid & 3;       // A fill: h=ha(0..63), k=kqa*4..+3
    const float* Xb = X + (size_t)b * CIN * TT;
    const float* Wr = Wl1 + (size_t)(h0 + ha) * TT + kqa * 4;

    // all 160 prow entries filled (zero-pad past CIN)
    for (int i = tid; i < 160; i += 256)
        prow[i] = (i < CIN) ? perm[i] : 0;
    __syncthreads();

    ull acc[4][5];
#pragma unroll
    for (int i = 0; i < 4; i++)
#pragma unroll
        for (int q = 0; q < 5; q++) acc[i][q] = 0ULL;

    // ---- prologue: slab 0 ----
    float4 va, vbx[3];
    va = *(const float4*)(Wr);
#pragma unroll
    for (int it = 0; it < 3; it++) {
        int idx = tid + 256 * it;                 // 0..767, valid < 640
        if (idx < 640) {
            int c = idx >> 2, kq = idx & 3;
            vbx[it] = *(const float4*)(Xb + (size_t)prow[c] * TT + kq * 4);
        }
    }
    {
        float* Ad = Af;
        int kb = kqa * 4;
        Ad[(kb+0)*68 + ha] = va.x;  Ad[(kb+1)*68 + ha] = va.y;
        Ad[(kb+2)*68 + ha] = va.z;  Ad[(kb+3)*68 + ha] = va.w;
        ull* Bd = Bsd;
#pragma unroll
        for (int it = 0; it < 3; it++) {
            int idx = tid + 256 * it;
            if (idx < 640) {
                int c = idx >> 2, kq = idx & 3;
                int p = c >> 1, hf = c & 1;
                ((float*)(Bd + (size_t)(kq*4+0)*81 + p))[hf] = vbx[it].x;
                ((float*)(Bd + (size_t)(kq*4+1)*81 + p))[hf] = vbx[it].y;
                ((float*)(Bd + (size_t)(kq*4+2)*81 + p))[hf] = vbx[it].z;
                ((float*)(Bd + (size_t)(kq*4+3)*81 + p))[hf] = vbx[it].w;
            }
        }
    }
    __syncthreads();

    for (int s = 0; s < TT / 16; s++) {
        const int buf = s & 1;
        const bool more = (s + 1 < TT / 16);
        if (more) {
            int k0 = (s + 1) * 16;
            va = *(const float4*)(Wr + k0);
#pragma unroll
            for (int it = 0; it < 3; it++) {
                int idx = tid + 256 * it;
                if (idx < 640) {
                    int c = idx >> 2, kq = idx & 3;
                    vbx[it] = *(const float4*)(Xb + (size_t)prow[c] * TT + k0 + kq * 4);
                }
            }
        }
        const float* Ab = Af + buf * (16 * 68);
        const ull*   Bb = Bsd + buf * (16 * 81);
#pragma unroll
        for (int k = 0; k < 16; k++) {
            float4 w0 = *(const float4*)(Ab + k * 68 + ty * 4);
            ull ad0 = dupf(w0.x), ad1 = dupf(w0.y),
                ad2 = dupf(w0.z), ad3 = dupf(w0.w);
            const ull* Br = Bb + k * 81;
            ull b0 = Br[tx], b1 = Br[tx+16], b2 = Br[tx+32],
                b3 = Br[tx+48], b4 = Br[tx+64];
            ffma2(acc[0][0], ad0, b0); ffma2(acc[1][0], ad1, b0);
            ffma2(acc[2][0], ad2, b0); ffma2(acc[3][0], ad3, b0);
            ffma2(acc[0][1], ad0, b1); ffma2(acc[1][1], ad1, b1);
            ffma2(acc[2][1], ad2, b1); ffma2(acc[3][1], ad3, b1);
            ffma2(acc[0][2], ad0, b2); ffma2(acc[1][2], ad1, b2);
            ffma2(acc[2][2], ad2, b2); ffma2(acc[3][2], ad3, b2);
            ffma2(acc[0][3], ad0, b3); ffma2(acc[1][3], ad1, b3);
            ffma2(acc[2][3], ad2, b3); ffma2(acc[3][3], ad3, b3);
            ffma2(acc[0][4], ad0, b4); ffma2(acc[1][4], ad1, b4);
            ffma2(acc[2][4], ad2, b4); ffma2(acc[3][4], ad3, b4);
        }
        if (more) {
            float* Ad = Af + (buf ^ 1) * (16 * 68);
            ull*   Bd = Bsd + (buf ^ 1) * (16 * 81);
            int kb = kqa * 4;
            Ad[(kb+0)*68 + ha] = va.x;  Ad[(kb+1)*68 + ha] = va.y;
            Ad[(kb+2)*68 + ha] = va.z;  Ad[(kb+3)*68 + ha] = va.w;
#pragma unroll
            for (int it = 0; it < 3; it++) {
                int idx = tid + 256 * it;
                if (idx < 640) {
                    int c = idx >> 2, kq = idx & 3;
                    int p = c >> 1, hf = c & 1;
                    ((float*)(Bd + (size_t)(kq*4+0)*81 + p))[hf] = vbx[it].x;
                    ((float*)(Bd + (size_t)(kq*4+1)*81 + p))[hf] = vbx[it].y;
                    ((float*)(Bd + (size_t)(kq*4+2)*81 + p))[hf] = vbx[it].z;
                    ((float*)(Bd + (size_t)(kq*4+3)*81 + p))[hf] = vbx[it].w;
                }
            }
            __syncthreads();
        }
    }

    // ---- epilogue: acc (pairs over c at p = tx+16q) -> Ct[h][c] ----
    __syncthreads();
#pragma unroll
    for (int i = 0; i < 4; i++)
#pragma unroll
        for (int q = 0; q < 5; q++) {
            float2 f = *(float2*)&acc[i][q];
            int p = tx + 16 * q;
            *(float2*)(Ct + (ty * 4 + i) * 162 + 2 * p) = f;
        }
    __syncthreads();

    // ---- fused psp scan over c + spike (threads 0..63, in-place) ----
    if (tid < 64) {
        float y = 0.0f;
        float* row = Ct + tid * 162;
#pragma unroll 4
        for (int c = 0; c < CIN; c++) {
            y = fmaf(ALPHA_F, y, row[c]);
            row[c] = (y >= THETA_F) ? 1.0f : 0.0f;
        }
    }
    __syncthreads();

    // ---- coalesced store to g_l1[b][c][h0..h0+63] ----
    float* dstb = g_l1 + (size_t)b * CIN * HID + h0;
#pragma unroll 4
    for (int idx = tid; idx < CIN * 64; idx += 256) {
        int c = idx >> 6, hh = idx & 63;
        dstb[(size_t)c * HID + hh] = Ct[hh * 162 + c];
    }
}

// ===========================================================================
// Branch1 layer2: a2[b,o,t] = sum_h W2[o,h] * s1u8[b,h,t]  (unchanged)
// ===========================================================================
__global__ __launch_bounds__(256) void k_gemm_b1l2(const float* __restrict__ W2) {
    __shared__ ull   Wsd[2][32 * 21];
    __shared__ float Ssf[2][32 * 132];

    const int b  = blockIdx.y;
    const int t0 = blockIdx.x * 128;
    const int tid = threadIdx.x;
    const int tx = tid & 63, ty = tid >> 6;
    const unsigned char* Sb = g_s1u8 + (size_t)b * HID * TT + t0;

    ull acc[5];
#pragma unroll
    for (int q = 0; q < 5; q++) acc[q] = 0ULL;

    float vwf[3];  uchar4 vu[4];

#pragma unroll
    for (int it = 0; it < 3; it++) {
        int idx = tid + 256 * it;
        if (idx < 640) vwf[it] = W2[(idx >> 5) * HID + (idx & 31)];
    }
#pragma unroll
    for (int it = 0; it < 4; it++) {
        int idx = tid + 256 * it;
        vu[it] = *(const uchar4*)(Sb + (size_t)(idx >> 5) * TT + (idx & 31) * 4);
    }
    {
#pragma unroll
        for (int it = 0; it < 3; it++) {
            int idx = tid + 256 * it;
            if (idx < 640) Wsd[0][(idx & 31) * 21 + (idx >> 5)] = dupf(vwf[it]);
        }
#pragma unroll
        for (int it = 0; it < 4; it++) {
            int idx = tid + 256 * it;
            *(float4*)&Ssf[0][(idx >> 5) * 132 + (idx & 31) * 4] =
                make_float4((float)vu[it].x, (float)vu[it].y,
                            (float)vu[it].z, (float)vu[it].w);
        }
    }
    __syncthreads();

    for (int s = 0; s < HID / 32; s++) {
        const int buf = s & 1;
        const bool more = (s + 1 < HID / 32);
        if (more) {
            int k0 = (s + 1) * 32;
#pragma unroll
            for (int it = 0; it < 3; it++) {
                int idx = tid + 256 * it;
                if (idx < 640) vwf[it] = W2[(idx >> 5) * HID + k0 + (idx & 31)];
            }
#pragma unroll
            for (int it = 0; it < 4; it++) {
                int idx = tid + 256 * it;
                vu[it] = *(const uchar4*)(Sb + (size_t)(k0 + (idx >> 5)) * TT
                                             + (idx & 31) * 4);
            }
        }
#pragma unroll
        for (int k = 0; k < 32; k++) {
            const ull* Ar = &Wsd[buf][k * 21 + ty * 5];
            ull a0 = Ar[0], a1 = Ar[1], a2 = Ar[2], a3 = Ar[3], a4 = Ar[4];
            ull bv = *((const ull*)&Ssf[buf][k * 132] + tx);
            ffma2(acc[0], a0, bv);
            ffma2(acc[1], a1, bv);
            ffma2(acc[2], a2, bv);
            ffma2(acc[3], a3, bv);
            ffma2(acc[4], a4, bv);
        }
        if (more) {
#pragma unroll
            for (int it = 0; it < 3; it++) {
                int idx = tid + 256 * it;
                if (idx < 640) Wsd[buf^1][(idx & 31) * 21 + (idx >> 5)] = dupf(vwf[it]);
            }
#pragma unroll
            for (int it = 0; it < 4; it++) {
                int idx = tid + 256 * it;
                *(float4*)&Ssf[buf^1][(idx >> 5) * 132 + (idx & 31) * 4] =
                    make_float4((float)vu[it].x, (float)vu[it].y,
                                (float)vu[it].z, (float)vu[it].w);
            }
            __syncthreads();
        }
    }

#pragma unroll
    for (int q = 0; q < 5; q++) {
        int o = ty * 5 + q;
        *(ull*)(g_a2 + ((size_t)b * NOUT + o) * TT + t0 + tx * 2) = acc[q];
    }
}

// ---------------------------------------------------------------------------
// Warp-per-row output scans (unchanged)
// ---------------------------------------------------------------------------
__device__ __forceinline__ void scan_rows(const float* __restrict__ in,
                                          float* __restrict__ out,
                                          int len, int out_off) {
    __shared__ float4 buf[8][32];
    const int w = threadIdx.x >> 5, lane = threadIdx.x & 31;
    const int row = blockIdx.x * 8 + w;
    const float* ip = in + (size_t)row * len;
    float* op = out + (size_t)row * OUTT + out_off;
    const int nch = (len + 127) / 128;

    float y = 0.0f;
    int idx = lane * 4;
    float4 v = make_float4(0.f, 0.f, 0.f, 0.f);
    if (idx < len) v = *(const float4*)(ip + idx);

    for (int ch = 0; ch < nch; ch++) {
        buf[w][lane] = v;
        __syncwarp();
        int nidx = (ch + 1) * 128 + lane * 4;
        if (nidx < len) v = *(const float4*)(ip + nidx);
        if (lane == 0) {
            int n4 = (len - ch * 128) >> 2; if (n4 > 32) n4 = 32;
            for (int i = 0; i < n4; i++) {
                float4 u = buf[w][i]; float4 s;
                y = fmaf(ALPHA_F, y, u.x); s.x = (y >= THETA_F) ? 1.0f : 0.0f;
                y = fmaf(ALPHA_F, y, u.y); s.y = (y >= THETA_F) ? 1.0f : 0.0f;
                y = fmaf(ALPHA_F, y, u.z); s.z = (y >= THETA_F) ? 1.0f : 0.0f;
                y = fmaf(ALPHA_F, y, u.w); s.w = (y >= THETA_F) ? 1.0f : 0.0f;
                buf[w][i] = s;
            }
        }
        __syncwarp();
        int oi = ch * 128 + lane * 4;
        if (oi < len) *(float4*)(op + oi) = buf[w][lane];
        __syncwarp();
    }
}

__global__ __launch_bounds__(256) void k_scan_a2(float* __restrict__ out) {
    scan_rows(g_a2, out, TT, 0);
}
__global__ __launch_bounds__(256) void k_scan_l2(float* __restrict__ out) {
    scan_rows(g_l2, out, CIN, TT);
}

// ---------------------------------------------------------------------------
// Branch2 layer2: l2[b,o,c] = sum_h Wl2[o,h] * l1[b,c,h]  (unchanged)
// ---------------------------------------------------------------------------
__global__ __launch_bounds__(160) void k_gemm_b2l2(const float* __restrict__ Wl2) {
    __shared__ float Ws[4 * HID];
    const int og = blockIdx.x;
    const int b  = blockIdx.y;
    const int tid = threadIdx.x;

    for (int idx = tid; idx < 4 * HID; idx += 160)
        Ws[idx] = Wl2[(og * 4 + (idx >> 9)) * HID + (idx & (HID - 1))];
    __syncthreads();

    const int c = tid;
    if (c >= CIN) return;
    const float* Lb = g_l1 + ((size_t)b * CIN + c) * HID;
    float acc[4] = {0.f, 0.f, 0.f, 0.f};

#pragma unroll 4
    for (int h = 0; h < HID; h += 4) {
        float4 xv = *(const float4*)(Lb + h);
#pragma unroll
        for (int o = 0; o < 4; o++) {
            const float4 w = *(const float4*)&Ws[o * HID + h];
            acc[o] = fmaf(w.x, xv.x, acc[o]);
            acc[o] = fmaf(w.y, xv.y, acc[o]);
            acc[o] = fmaf(w.z, xv.z, acc[o]);
            acc[o] = fmaf(w.w, xv.w, acc[o]);
        }
    }
#pragma unroll
    for (int o = 0; o < 4; o++)
        g_l2[((size_t)b * NOUT + og * 4 + o) * CIN + c] = acc[o];
}

// ---------------------------------------------------------------------------
// Launch: fork branch-2 onto a secondary stream, join before return.
// ---------------------------------------------------------------------------
extern "C" void kernel_launch(void* const* d_in, const int* in_sizes, int n_in,
                              void* d_out, int out_size) {
    (void)in_sizes; (void)n_in; (void)out_size;
    const float* X    = (const float*)d_in[0];
    const float* W1   = (const float*)d_in[1];
    const float* W2   = (const float*)d_in[2];
    const float* Wl1  = (const float*)d_in[3];
    const float* Wl2  = (const float*)d_in[4];
    const int*   perm = (const int*)d_in[5];
    float* out = (float*)d_out;

    static cudaStream_t s2 = [] {
        cudaStream_t s; cudaStreamCreateWithFlags(&s, cudaStreamNonBlocking); return s;
    }();
    static cudaEvent_t evFork = [] {
        cudaEvent_t e; cudaEventCreateWithFlags(&e, cudaEventDisableTiming); return e;
    }();
    static cudaEvent_t evJoin = [] {
        cudaEvent_t e; cudaEventCreateWithFlags(&e, cudaEventDisableTiming); return e;
    }();

    cudaFuncSetAttribute(k_b1l1_psp, cudaFuncAttributeMaxDynamicSharedMemorySize, B1_SMEM);
    cudaFuncSetAttribute(k_b2l1_psp, cudaFuncAttributeMaxDynamicSharedMemorySize, B2_SMEM);

    // fork: branch 2 on s2
    cudaEventRecord(evFork, 0);
    cudaStreamWaitEvent(s2, evFork, 0);
    k_b2l1_psp<<<dim3(HID / 64, BB), 256, B2_SMEM, s2>>>(X, Wl1, perm);
    k_gemm_b2l2<<<dim3(5, BB), 160, 0, s2>>>(Wl2);
    k_scan_l2<<<BB * NOUT / 8, 256, 0, s2>>>(out);
    cudaEventRecord(evJoin, s2);

    // branch 1 on the main stream
    k_b1l1_psp<<<dim3(HID / 64, BB), 256, B1_SMEM>>>(X, W1);
    k_gemm_b1l2<<<dim3(TT / 128, BB), 256>>>(W2);
    k_scan_a2<<<BB * NOUT / 8, 256>>>(out);

    // join
    cudaStreamWaitEvent(0, evJoin, 0);
}